// round 15
// baseline (speedup 1.0000x reference)
#include <cuda_runtime.h>
#include <cuda_fp16.h>
#include <math.h>
#include <stdint.h>

// Problem constants
#define Bz   4
#define Nn   1024
#define Dd   1024
#define Hh   8
#define DKk  128
#define EPSf 1e-6f

static const long long AT_OFF  = (long long)Bz * Nn * Dd;                 // 4194304
static const long long AF_OFF  = AT_OFF + (long long)Bz * Hh * Nn * Nn;  // 37748736

#define PROJ_ELEMS ((long long)Bz * Hh * Nn * DKk)   // 4194304
__device__ __half g_qt[PROJ_ELEMS];
__device__ __half g_kt[PROJ_ELEMS];
__device__ __half g_qf[PROJ_ELEMS];
__device__ __half g_kf[PROJ_ELEMS];
__device__ __half g_vvT[PROJ_ELEMS];                  // [z][d][n] transposed
__device__ __half g_prefc[(long long)Bz * Nn * Dd];
__device__ float  g_preln[(long long)Bz * Nn * Dd];
__device__ float  g_afp[(long long)32 * 8 * DKk * DKk];     // split-K partials
__device__ __half g_at16[(long long)Bz * Hh * Nn * Nn];     // fp16 logits / attn
__device__ __half g_af16[(long long)32 * DKk * DKk];        // fp16 feat-attn copy
__device__ __half g_wh[6u * 1048576u];                      // fp16 weights
__device__ __half g_xh[5u * 4194304u];                      // fp16 inputs

__device__ __forceinline__ void cp_async16(void* dst, const void* src) {
    uint32_t s = (uint32_t)__cvta_generic_to_shared(dst);
    asm volatile("cp.async.cg.shared.global [%0], [%1], 16;" :: "r"(s), "l"(src));
}
__device__ __forceinline__ void cp_commit() {
    asm volatile("cp.async.commit_group;" ::: "memory");
}
__device__ __forceinline__ uint32_t pack_h2(const __half* lo, const __half* hi) {
    uint32_t u0 = *(const unsigned short*)lo;
    uint32_t u1 = *(const unsigned short*)hi;
    return u0 | (u1 << 16);
}
__device__ __forceinline__ uint32_t f2_to_h2(float x, float y) {
    __half2 h = __floats2half2_rn(x, y);
    return *(uint32_t*)&h;
}
__device__ __forceinline__ void ldsm_x4(uint32_t& r0, uint32_t& r1, uint32_t& r2, uint32_t& r3,
                                        uint32_t addr) {
    asm volatile("ldmatrix.sync.aligned.m8n8.x4.shared.b16 {%0,%1,%2,%3}, [%4];"
                 : "=r"(r0), "=r"(r1), "=r"(r2), "=r"(r3) : "r"(addr));
}

// One launch: convert 6 weight matrices + 5 input tensors to fp16.
__global__ void cvt_all_kernel(const float* w0, const float* w1, const float* w2,
                               const float* w3, const float* w4, const float* w5,
                               const float* x0, const float* x1, const float* x2,
                               const float* x3, const float* x4,
                               __half* wh, __half* xh) {
    int b = blockIdx.x;
    if (b < 6144) {
        const int t = b >> 10;
        const float* src;
        switch (t) {
            case 0: src = w0; break;  case 1: src = w1; break;
            case 2: src = w2; break;  case 3: src = w3; break;
            case 4: src = w4; break;  default: src = w5; break;
        }
        const long long e4 = (long long)(b & 1023) * 256 + threadIdx.x;
        float4 v = *(const float4*)(src + e4 * 4);
        *(uint2*)(wh + (long long)t * 1048576 + e4 * 4) =
            make_uint2(f2_to_h2(v.x, v.y), f2_to_h2(v.z, v.w));
    } else {
        b -= 6144;
        const int t = b >> 12;
        const float* src;
        switch (t) {
            case 0: src = x0; break;  case 1: src = x1; break;
            case 2: src = x2; break;  case 3: src = x3; break;
            default: src = x4; break;
        }
        const long long e4 = (long long)(b & 4095) * 256 + threadIdx.x;
        float4 v = *(const float4*)(src + e4 * 4);
        *(uint2*)(xh + (long long)t * 4194304 + e4 * 4) =
            make_uint2(f2_to_h2(v.x, v.y), f2_to_h2(v.z, v.w));
    }
}

// ---------------------------------------------------------------------------
// FP16 tensor-core GEMM body (3-stage cp.async). TBK=32, 128 thr = 4 warps
// (2x2), warp tile 64x64, mma m16n8k16 -> f32. ldmatrix for mode-0 operands.
//   AMODE 0: A [M,K] rm          AMODE 1: A [K,M] rm (A^T)
//   BMODE 0: B [N,K] rm (B^T)    BMODE 1: B [K,N] rm
//   CH 1: write C fp16 (else fp32 with optional residual R)
//   CT 1: write transposed fp16 C via smem staging
//   FUSE 1: after mainloop, multiply tile by af (Ct, K-major 128x128 fp16),
//           write fp16 product to Cb.
//   AECHO 1: echo each A smem tile as fp32 to Aecho (write-once streaming).
// ---------------------------------------------------------------------------
#define TBM 128
#define TBN 128
#define TBK 32
#define NSTG 3
#define SMEM_ALL 61440
#define SMEM_FUSE 70656
#define SMEM_LOG  70656

template<int AMODE, int BMODE, int CH, int CT, int FUSE, int AECHO>
__device__ __forceinline__ void gemm_f16(
    char* __restrict__ smem,
    const __half* __restrict__ Ab, const __half* __restrict__ Bb,
    void* __restrict__ Cb, const float* __restrict__ R,
    __half* __restrict__ Ct, int ldt,
    float* __restrict__ Aecho, int lde,
    int K, int lda, int ldb, int ldc, float alpha,
    int row0, int col0)
{
    constexpr int ASZB = (AMODE == 0) ? 128 * 40 * 2 : 32 * 136 * 2;
    constexpr int BSZB = (BMODE == 0) ? 128 * 40 * 2 : 32 * 136 * 2;

    char* sAb = smem;
    char* sBb = smem + NSTG * ASZB;

    const int tid  = threadIdx.x;
    const int lane = tid & 31;
    const int warp = tid >> 5;
    const int wm = (warp >> 1) * 64;
    const int wn = (warp & 1) * 64;
    const int g  = lane >> 2;
    const int t4 = lane & 3;
    const int lrow = lane & 7;
    const int lsel = lane >> 3;

    float acc[4][8][4];
    #pragma unroll
    for (int i = 0; i < 4; i++)
        #pragma unroll
        for (int j = 0; j < 8; j++)
            #pragma unroll
            for (int k = 0; k < 4; k++) acc[i][j][k] = 0.f;

    const int nIter = K / TBK;

    auto load_stage = [&](int buf, int k0) {
        if (AMODE == 0) {
            __half* dA = (__half*)(sAb + buf * ASZB);
            #pragma unroll
            for (int it = 0; it < 4; it++) {
                int f = tid + it * 128;
                int row = f >> 2, seg = (f & 3) * 8;
                cp_async16(&dA[row * 40 + seg], Ab + (long long)(row0 + row) * lda + k0 + seg);
            }
        } else {
            __half* dA = (__half*)(sAb + buf * ASZB);
            #pragma unroll
            for (int it = 0; it < 4; it++) {
                int f = tid + it * 128;
                int k = f >> 4, seg = (f & 15) * 8;
                cp_async16(&dA[k * 136 + seg], Ab + (long long)(k0 + k) * lda + row0 + seg);
            }
        }
        if (BMODE == 0) {
            __half* dB = (__half*)(sBb + buf * BSZB);
            #pragma unroll
            for (int it = 0; it < 4; it++) {
                int f = tid + it * 128;
                int row = f >> 2, seg = (f & 3) * 8;
                cp_async16(&dB[row * 40 + seg], Bb + (long long)(col0 + row) * ldb + k0 + seg);
            }
        } else {
            __half* dB = (__half*)(sBb + buf * BSZB);
            #pragma unroll
            for (int it = 0; it < 4; it++) {
                int f = tid + it * 128;
                int k = f >> 4, seg = (f & 15) * 8;
                cp_async16(&dB[k * 136 + seg], Bb + (long long)(k0 + k) * ldb + col0 + seg);
            }
        }
        cp_commit();
    };

    #pragma unroll
    for (int s = 0; s < NSTG; s++) load_stage(s, s * TBK);

    for (int it = 0; it < nIter; it++) {
        const int rem = nIter - 1 - it;
        if (rem >= 2)      asm volatile("cp.async.wait_group 2;" ::: "memory");
        else if (rem == 1) asm volatile("cp.async.wait_group 1;" ::: "memory");
        else               asm volatile("cp.async.wait_group 0;" ::: "memory");
        __syncthreads();

        const int cb = it % NSTG;
        const char* cAb = sAb + cb * ASZB;
        const char* cBb = sBb + cb * BSZB;
        const uint32_t sAu = (uint32_t)__cvta_generic_to_shared(cAb);
        const uint32_t sBu = (uint32_t)__cvta_generic_to_shared(cBb);

        #pragma unroll
        for (int kk = 0; kk < TBK; kk += 16) {
            uint32_t a[4][4], b[8][2];
            if (AMODE == 0) {
                #pragma unroll
                for (int mt = 0; mt < 4; mt++) {
                    int row = wm + mt * 16 + ((lsel & 1) << 3) + lrow;
                    int kc  = kk + ((lsel >> 1) << 3);
                    ldsm_x4(a[mt][0], a[mt][1], a[mt][2], a[mt][3],
                            sAu + (uint32_t)(row * 40 + kc) * 2u);
                }
            } else {
                const __half* cA = (const __half*)cAb;
                #pragma unroll
                for (int mt = 0; mt < 4; mt++) {
                    int mb = wm + mt * 16;
                    int kr = kk + 2 * t4;
                    a[mt][0] = pack_h2(&cA[kr * 136 + mb + g],       &cA[(kr + 1) * 136 + mb + g]);
                    a[mt][1] = pack_h2(&cA[kr * 136 + mb + g + 8],   &cA[(kr + 1) * 136 + mb + g + 8]);
                    a[mt][2] = pack_h2(&cA[(kr + 8) * 136 + mb + g], &cA[(kr + 9) * 136 + mb + g]);
                    a[mt][3] = pack_h2(&cA[(kr + 8) * 136 + mb + g + 8], &cA[(kr + 9) * 136 + mb + g + 8]);
                }
            }
            if (BMODE == 0) {
                #pragma unroll
                for (int p = 0; p < 4; p++) {
                    int row = wn + p * 16 + ((lsel >> 1) << 3) + lrow;
                    int kc  = kk + ((lsel & 1) << 3);
                    ldsm_x4(b[2 * p][0], b[2 * p][1], b[2 * p + 1][0], b[2 * p + 1][1],
                            sBu + (uint32_t)(row * 40 + kc) * 2u);
                }
            } else {
                const __half* cB = (const __half*)cBb;
                #pragma unroll
                for (int nt = 0; nt < 8; nt++) {
                    int nb = wn + nt * 8 + g;
                    int kr = kk + 2 * t4;
                    b[nt][0] = pack_h2(&cB[kr * 136 + nb],       &cB[(kr + 1) * 136 + nb]);
                    b[nt][1] = pack_h2(&cB[(kr + 8) * 136 + nb], &cB[(kr + 9) * 136 + nb]);
                }
            }
            #pragma unroll
            for (int mt = 0; mt < 4; mt++)
                #pragma unroll
                for (int nt = 0; nt < 8; nt++) {
                    asm volatile(
                        "mma.sync.aligned.m16n8k16.row.col.f32.f16.f16.f32 "
                        "{%0,%1,%2,%3}, {%4,%5,%6,%7}, {%8,%9}, {%0,%1,%2,%3};"
                        : "+f"(acc[mt][nt][0]), "+f"(acc[mt][nt][1]),
                          "+f"(acc[mt][nt][2]), "+f"(acc[mt][nt][3])
                        : "r"(a[mt][0]), "r"(a[mt][1]), "r"(a[mt][2]), "r"(a[mt][3]),
                          "r"(b[nt][0]), "r"(b[nt][1]));
                }
        }
        if (AECHO && AMODE == 0) {
            const __half* cA2 = (const __half*)cAb;
            const int k0 = it * TBK;
            #pragma unroll
            for (int i = 0; i < 4; i++) {
                int f = tid + i * 128;
                int row = f >> 2, seg = (f & 3) * 8;
                const __half* src = &cA2[row * 40 + seg];
                float4 lo = make_float4(__half2float(src[0]), __half2float(src[1]),
                                        __half2float(src[2]), __half2float(src[3]));
                float4 hi = make_float4(__half2float(src[4]), __half2float(src[5]),
                                        __half2float(src[6]), __half2float(src[7]));
                float* dst = Aecho + (long long)(row0 + row) * lde + k0 + seg;
                __stwt((float4*)dst, lo);
                __stwt((float4*)(dst + 4), hi);
            }
        }
        __syncthreads();
        if (it + NSTG < nIter) load_stage(cb, (it + NSTG) * TBK);
    }

    if (FUSE) {
        __half* stA = (__half*)smem;                 // [128][136]
        __half* stB = (__half*)(smem + 34816);       // [128][136]
        #pragma unroll
        for (int i = 0; i < 16; i++) {
            int f = tid + i * 128;
            int row = f >> 4, seg = (f & 15) * 8;
            cp_async16(&stB[row * 136 + seg], Ct + row * 128 + seg);
        }
        cp_commit();
        #pragma unroll
        for (int mt = 0; mt < 4; mt++) {
            int rl = wm + mt * 16 + g;
            #pragma unroll
            for (int nt = 0; nt < 8; nt++) {
                int c = wn + nt * 8 + t4 * 2;
                *(uint32_t*)&stA[rl * 136 + c]       = f2_to_h2(acc[mt][nt][0], acc[mt][nt][1]);
                *(uint32_t*)&stA[(rl + 8) * 136 + c] = f2_to_h2(acc[mt][nt][2], acc[mt][nt][3]);
            }
        }
        asm volatile("cp.async.wait_group 0;" ::: "memory");
        __syncthreads();

        float ac2[4][8][4];
        #pragma unroll
        for (int i = 0; i < 4; i++)
            #pragma unroll
            for (int j = 0; j < 8; j++)
                #pragma unroll
                for (int k = 0; k < 4; k++) ac2[i][j][k] = 0.f;

        #pragma unroll
        for (int kk = 0; kk < 128; kk += 16) {
            uint32_t a[4][4], b[8][2];
            #pragma unroll
            for (int mt = 0; mt < 4; mt++) {
                int mb = wm + mt * 16 + g;
                a[mt][0] = *(const uint32_t*)&stA[mb * 136 + kk + 2 * t4];
                a[mt][1] = *(const uint32_t*)&stA[(mb + 8) * 136 + kk + 2 * t4];
                a[mt][2] = *(const uint32_t*)&stA[mb * 136 + kk + 2 * t4 + 8];
                a[mt][3] = *(const uint32_t*)&stA[(mb + 8) * 136 + kk + 2 * t4 + 8];
            }
            #pragma unroll
            for (int nt = 0; nt < 8; nt++) {
                int nb = wn + nt * 8 + g;
                int kr = kk + 2 * t4;
                b[nt][0] = pack_h2(&stB[kr * 136 + nb],       &stB[(kr + 1) * 136 + nb]);
                b[nt][1] = pack_h2(&stB[(kr + 8) * 136 + nb], &stB[(kr + 9) * 136 + nb]);
            }
            #pragma unroll
            for (int mt = 0; mt < 4; mt++)
                #pragma unroll
                for (int nt = 0; nt < 8; nt++) {
                    asm volatile(
                        "mma.sync.aligned.m16n8k16.row.col.f32.f16.f16.f32 "
                        "{%0,%1,%2,%3}, {%4,%5,%6,%7}, {%8,%9}, {%0,%1,%2,%3};"
                        : "+f"(ac2[mt][nt][0]), "+f"(ac2[mt][nt][1]),
                          "+f"(ac2[mt][nt][2]), "+f"(ac2[mt][nt][3])
                        : "r"(a[mt][0]), "r"(a[mt][1]), "r"(a[mt][2]), "r"(a[mt][3]),
                          "r"(b[nt][0]), "r"(b[nt][1]));
                }
        }
        __half* Ch = (__half*)Cb;
        #pragma unroll
        for (int mt = 0; mt < 4; mt++) {
            int r0g = row0 + wm + mt * 16 + g;
            #pragma unroll
            for (int nt = 0; nt < 8; nt++) {
                int c0g = wn + nt * 8 + t4 * 2;
                *(uint32_t*)(Ch + (long long)r0g * ldc + c0g)       = f2_to_h2(ac2[mt][nt][0], ac2[mt][nt][1]);
                *(uint32_t*)(Ch + (long long)(r0g + 8) * ldc + c0g) = f2_to_h2(ac2[mt][nt][2], ac2[mt][nt][3]);
            }
        }
        return;
    }

    if (CT) {
        __half* st = (__half*)smem;
        #pragma unroll
        for (int mt = 0; mt < 4; mt++) {
            int rl = wm + mt * 16 + g;
            #pragma unroll
            for (int nt = 0; nt < 8; nt++) {
                int c = wn + nt * 8 + t4 * 2;
                st[c * 136 + rl]            = __float2half_rn(acc[mt][nt][0] * alpha);
                st[(c + 1) * 136 + rl]      = __float2half_rn(acc[mt][nt][1] * alpha);
                st[c * 136 + rl + 8]        = __float2half_rn(acc[mt][nt][2] * alpha);
                st[(c + 1) * 136 + rl + 8]  = __float2half_rn(acc[mt][nt][3] * alpha);
            }
        }
        __syncthreads();
        #pragma unroll
        for (int it2 = 0; it2 < 16; it2++) {
            int i = tid + it2 * 128;
            int d = i >> 4, seg = (i & 15) * 8;
            *(uint4*)(Ct + (long long)d * ldt + row0 + seg) = *(const uint4*)&st[d * 136 + seg];
        }
        return;
    }

    #pragma unroll
    for (int mt = 0; mt < 4; mt++) {
        int r0g = row0 + wm + mt * 16 + g;
        #pragma unroll
        for (int nt = 0; nt < 8; nt++) {
            int c0g = col0 + wn + nt * 8 + t4 * 2;
            float v0 = acc[mt][nt][0] * alpha;
            float v1 = acc[mt][nt][1] * alpha;
            float v2 = acc[mt][nt][2] * alpha;
            float v3 = acc[mt][nt][3] * alpha;
            if (CH) {
                __half* Ch = (__half*)Cb;
                *(uint32_t*)(Ch + (long long)r0g * ldc + c0g)       = f2_to_h2(v0, v1);
                *(uint32_t*)(Ch + (long long)(r0g + 8) * ldc + c0g) = f2_to_h2(v2, v3);
            } else {
                float* Cf = (float*)Cb;
                if (R) {
                    v0 += R[(long long)r0g * ldc + c0g];
                    v1 += R[(long long)r0g * ldc + c0g + 1];
                    v2 += R[(long long)(r0g + 8) * ldc + c0g];
                    v3 += R[(long long)(r0g + 8) * ldc + c0g + 1];
                }
                *(float2*)(Cf + (long long)r0g * ldc + c0g)       = make_float2(v0, v1);
                *(float2*)(Cf + (long long)(r0g + 8) * ldc + c0g) = make_float2(v2, v3);
            }
        }
    }
}

// ---------------------------------------------------------------------------
// Kernels
// ---------------------------------------------------------------------------

// All 5 projections, fp16 in/out. z in [0,160): p = z/32, zz = z%32 = (b,h).
__global__ void __launch_bounds__(128, 3)
proj_gemm(const __half* __restrict__ xh, const __half* __restrict__ wh,
          __half* qt, __half* kt, __half* qf, __half* kf, __half* vvT) {
    extern __shared__ char dynsmem[];
    const int z = blockIdx.z;
    const int p = z >> 5, zz = z & 31;
    const __half* Ab = xh + (long long)p * 4194304 + (long long)(zz >> 3) * Nn * Dd;
    const __half* Bb = wh + (long long)p * 1048576 + (long long)(zz & 7) * DKk * Dd;
    const int row0 = blockIdx.y * TBM;
    if (p == 4) {
        gemm_f16<0, 0, 1, 1, 0, 0>(dynsmem, Ab, Bb, nullptr, nullptr,
                                   vvT + (long long)zz * DKk * Nn, Nn, nullptr, 0,
                                   Dd, Dd, Dd, DKk, 1.0f, row0, 0);
    } else {
        __half* C;
        switch (p) {
            case 0: C = qt; break;  case 1: C = kt; break;
            case 2: C = qf; break;  default: C = kf; break;
        }
        gemm_f16<0, 0, 1, 0, 0, 0>(dynsmem, Ab, Bb,
                                   C + (long long)zz * Nn * DKk, nullptr, nullptr, 0, nullptr, 0,
                                   Dd, Dd, Dd, DKk, 1.0f, row0, 0);
    }
}

// time logits via A-resident strips (512 CTAs: z * 8 rowtiles * 2 colgroups,
// 4 column tiles each) + feature split-K partials (256 CTAs).
__global__ void __launch_bounds__(128, 3)
fused_logits(const __half* __restrict__ qt, const __half* __restrict__ kt,
             const __half* __restrict__ qf, const __half* __restrict__ kf,
             __half* __restrict__ at16, float* __restrict__ afp, float alpha) {
    extern __shared__ char dynsmem[];
    const int bx = blockIdx.x;
    if (bx < 512) {
        const int z = bx >> 4, rowtile = (bx >> 1) & 7, cg = bx & 1;
        const int row0 = rowtile * 128;
        const __half* A  = qt + (long long)z * 131072 + (long long)row0 * 128;
        const __half* Bk = kt + (long long)z * 131072;
        __half* Cz = at16 + (long long)z * Nn * Nn;

        __half* As = (__half*)dynsmem;             // [128][136]
        __half* Bs = (__half*)(dynsmem + 34816);   // [128][136]
        const int tid = threadIdx.x;
        const int lane = tid & 31, warp = tid >> 5;
        const int wm = (warp >> 1) * 64, wn = (warp & 1) * 64;
        const int g = lane >> 2, t4 = lane & 3;
        const int lrow = lane & 7, lsel = lane >> 3;
        const uint32_t sAu = (uint32_t)__cvta_generic_to_shared(As);
        const uint32_t sBu = (uint32_t)__cvta_generic_to_shared(Bs);

        // load A strip, full K=128
        #pragma unroll
        for (int i = 0; i < 16; i++) {
            int f = tid + i * 128;
            int row = f >> 4, seg = (f & 15) * 8;
            cp_async16(&As[row * 136 + seg], A + (long long)row * 128 + seg);
        }
        cp_commit();

        for (int ct = 0; ct < 4; ct++) {
            const int col0 = (cg * 4 + ct) * 128;
            #pragma unroll
            for (int i = 0; i < 16; i++) {
                int f = tid + i * 128;
                int row = f >> 4, seg = (f & 15) * 8;
                cp_async16(&Bs[row * 136 + seg], Bk + (long long)(col0 + row) * 128 + seg);
            }
            cp_commit();
            asm volatile("cp.async.wait_group 0;" ::: "memory");
            __syncthreads();

            float acc[4][8][4];
            #pragma unroll
            for (int i = 0; i < 4; i++)
                #pragma unroll
                for (int j = 0; j < 8; j++)
                    #pragma unroll
                    for (int k = 0; k < 4; k++) acc[i][j][k] = 0.f;

            #pragma unroll
            for (int kk = 0; kk < 128; kk += 16) {
                uint32_t a[4][4], b[8][2];
                #pragma unroll
                for (int mt = 0; mt < 4; mt++) {
                    int row = wm + mt * 16 + ((lsel & 1) << 3) + lrow;
                    int kc  = kk + ((lsel >> 1) << 3);
                    ldsm_x4(a[mt][0], a[mt][1], a[mt][2], a[mt][3],
                            sAu + (uint32_t)(row * 136 + kc) * 2u);
                }
                #pragma unroll
                for (int p2 = 0; p2 < 4; p2++) {
                    int row = wn + p2 * 16 + ((lsel >> 1) << 3) + lrow;
                    int kc  = kk + ((lsel & 1) << 3);
                    ldsm_x4(b[2 * p2][0], b[2 * p2][1], b[2 * p2 + 1][0], b[2 * p2 + 1][1],
                            sBu + (uint32_t)(row * 136 + kc) * 2u);
                }
                #pragma unroll
                for (int mt = 0; mt < 4; mt++)
                    #pragma unroll
                    for (int nt = 0; nt < 8; nt++) {
                        asm volatile(
                            "mma.sync.aligned.m16n8k16.row.col.f32.f16.f16.f32 "
                            "{%0,%1,%2,%3}, {%4,%5,%6,%7}, {%8,%9}, {%0,%1,%2,%3};"
                            : "+f"(acc[mt][nt][0]), "+f"(acc[mt][nt][1]),
                              "+f"(acc[mt][nt][2]), "+f"(acc[mt][nt][3])
                            : "r"(a[mt][0]), "r"(a[mt][1]), "r"(a[mt][2]), "r"(a[mt][3]),
                              "r"(b[nt][0]), "r"(b[nt][1]));
                    }
            }
            // epilogue: scaled fp16 direct to at16
            #pragma unroll
            for (int mt = 0; mt < 4; mt++) {
                int r0g = row0 + wm + mt * 16 + g;
                #pragma unroll
                for (int nt = 0; nt < 8; nt++) {
                    int c0g = col0 + wn + nt * 8 + t4 * 2;
                    *(uint32_t*)(Cz + (long long)r0g * Nn + c0g) =
                        f2_to_h2(acc[mt][nt][0] * alpha, acc[mt][nt][1] * alpha);
                    *(uint32_t*)(Cz + (long long)(r0g + 8) * Nn + c0g) =
                        f2_to_h2(acc[mt][nt][2] * alpha, acc[mt][nt][3] * alpha);
                }
            }
            __syncthreads();   // Bs consumed before next overwrite
        }
    } else {
        const int e = bx - 512;
        const int z = e >> 3, sub = e & 7;
        const long long base = (long long)z * Nn * DKk + (long long)sub * 128 * DKk;
        gemm_f16<1, 1, 0, 0, 0, 0>(dynsmem,
                        qf + base, kf + base,
                        afp + (long long)e * DKk * DKk, nullptr, nullptr, 0, nullptr, 0,
                        128, DKk, DKk, DKk, alpha, 0, 0);
    }
}

// fused: prefc tile = (at16 @ vvT^T) @ af16, written to prefc; echoes attn fp32.
__global__ void __launch_bounds__(128, 3)
attnv_fused(const __half* __restrict__ at16, const __half* __restrict__ vvT,
            const __half* __restrict__ af16, __half* __restrict__ prefc,
            float* __restrict__ at_out) {
    extern __shared__ char dynsmem[];
    const int z = blockIdx.z;
    gemm_f16<0, 0, 1, 0, 1, 1>(dynsmem,
                    at16 + (long long)z * Nn * Nn,
                    vvT + (long long)z * DKk * Nn,
                    prefc + (long long)(z >> 3) * Nn * Dd + (z & 7) * DKk,
                    nullptr,
                    (__half*)(af16 + (long long)z * DKk * DKk), 0,
                    at_out + (long long)z * Nn * Nn, Nn,
                    Nn, Nn, Nn, Dd, 1.0f, blockIdx.y * TBM, 0);
}

// preln = prefc @ w_fc^T + v
__global__ void __launch_bounds__(128, 3)
fc_gemm(const __half* __restrict__ prefc, const __half* __restrict__ wfc,
        float* __restrict__ preln, const float* __restrict__ v) {
    extern __shared__ char dynsmem[];
    gemm_f16<0, 0, 0, 0, 0, 0>(dynsmem, prefc, wfc, preln, v, nullptr, 0, nullptr, 0,
                    Dd, Dd, Dd, Dd, 1.0f,
                    blockIdx.y * TBM, blockIdx.x * TBN);
}

// ---------------------------------------------------------------------------
__device__ __forceinline__ float block_reduce(float v, bool is_max) {
    __shared__ float sh[32];
    int lane = threadIdx.x & 31, w = threadIdx.x >> 5;
    #pragma unroll
    for (int o = 16; o > 0; o >>= 1) {
        float o2 = __shfl_xor_sync(0xffffffff, v, o);
        v = is_max ? fmaxf(v, o2) : v + o2;
    }
    if (lane == 0) sh[w] = v;
    __syncthreads();
    int nw = (blockDim.x + 31) >> 5;
    v = (lane < nw) ? sh[lane] : (is_max ? -3.4e38f : 0.f);
    if (w == 0) {
        #pragma unroll
        for (int o = 16; o > 0; o >>= 1) {
            float o2 = __shfl_xor_sync(0xffffffff, v, o);
            v = is_max ? fmaxf(v, o2) : v + o2;
        }
        if (lane == 0) sh[0] = v;
    }
    __syncthreads();
    v = sh[0];
    __syncthreads();
    return v;
}

// Merged softmax launch. Time rows: no max-subtraction (logits bounded);
// masked lanes contribute 0. Writes normalized fp16 in place.
__global__ void softmax_all_kernel(__half* __restrict__ at16,
                                   const int* __restrict__ mask,
                                   const float* __restrict__ afp,
                                   float* __restrict__ S,
                                   __half* __restrict__ S16) {
    if (blockIdx.x < 32768) {
        const int r = blockIdx.x;
        const int b = r / (Hh * Nn);
        const int n = r % Nn;
        __half* row16 = at16 + (long long)r * Nn;
        const int* mrow = mask + ((long long)b * Nn + n) * Nn;
        const int j0 = threadIdx.x * 8;

        uint4 lv = *(const uint4*)(row16 + j0);
        __half2 h0 = *(__half2*)&lv.x, h1 = *(__half2*)&lv.y;
        __half2 h2 = *(__half2*)&lv.z, h3 = *(__half2*)&lv.w;
        int4 m0 = __ldg((const int4*)(mrow + j0));
        int4 m1 = __ldg((const int4*)(mrow + j0 + 4));
        float x[8];
        x[0] = m0.x == 0 ? 0.f : __expf(__low2float(h0));
        x[1] = m0.y == 0 ? 0.f : __expf(__high2float(h0));
        x[2] = m0.z == 0 ? 0.f : __expf(__low2float(h1));
        x[3] = m0.w == 0 ? 0.f : __expf(__high2float(h1));
        x[4] = m1.x == 0 ? 0.f : __expf(__low2float(h2));
        x[5] = m1.y == 0 ? 0.f : __expf(__high2float(h2));
        x[6] = m1.z == 0 ? 0.f : __expf(__low2float(h3));
        x[7] = m1.w == 0 ? 0.f : __expf(__high2float(h3));
        float s = 0.f;
        #pragma unroll
        for (int i = 0; i < 8; i++) s += x[i];
        s = block_reduce(s, false);
        float inv = 1.f / s;
        #pragma unroll
        for (int i = 0; i < 8; i++) x[i] *= inv;
        uint4 ov = make_uint4(f2_to_h2(x[0], x[1]), f2_to_h2(x[2], x[3]),
                              f2_to_h2(x[4], x[5]), f2_to_h2(x[6], x[7]));
        *(uint4*)(row16 + j0) = ov;
    } else {
        const int e = blockIdx.x - 32768;
        const int z = e >> 7;
        const int row = e & 127;
        const int t = threadIdx.x;
        float v = 0.f;
        #pragma unroll
        for (int s8 = 0; s8 < 8; s8++)
            v += afp[(((long long)z * 8 + s8) * DKk + row) * DKk + t];
        float mx = block_reduce(v, true);
        float ex = __expf(v - mx);
        float s = block_reduce(ex, false);
        float o = ex / s;
        __stwt(&S[((long long)z * DKk + row) * DKk + t], o);
        S16[((long long)z * DKk + row) * DKk + t] = __float2half_rn(o);
    }
}

__global__ void layernorm_kernel(const float* __restrict__ X, float* __restrict__ O,
                                 const float* __restrict__ gamma, const float* __restrict__ beta) {
    const int r = blockIdx.x;
    const float* row = X + (long long)r * Dd;
    float* orow = O + (long long)r * Dd;
    const int j0 = threadIdx.x * 4;
    float4 xv = *(const float4*)(row + j0);
    float x[4] = {xv.x, xv.y, xv.z, xv.w};
    float s = x[0] + x[1] + x[2] + x[3];
    float s2 = x[0]*x[0] + x[1]*x[1] + x[2]*x[2] + x[3]*x[3];
    s = block_reduce(s, false);
    s2 = block_reduce(s2, false);
    float mean = s * (1.f / Dd);
    float var = s2 * (1.f / Dd) - mean * mean;
    float inv = rsqrtf(var + EPSf);
    float4 gv = *(const float4*)(gamma + j0);
    float4 bv = *(const float4*)(beta + j0);
    __stwt((float4*)(orow + j0),
           make_float4((x[0] - mean) * inv * gv.x + bv.x,
                       (x[1] - mean) * inv * gv.y + bv.y,
                       (x[2] - mean) * inv * gv.z + bv.z,
                       (x[3] - mean) * inv * gv.w + bv.w));
}

// ---------------------------------------------------------------------------
extern "C" void kernel_launch(void* const* d_in, const int* in_sizes, int n_in,
                              void* d_out, int out_size) {
    const float* q_time    = (const float*)d_in[0];
    const float* k_time    = (const float*)d_in[1];
    const float* q_feature = (const float*)d_in[2];
    const float* k_feature = (const float*)d_in[3];
    const float* v         = (const float*)d_in[4];
    const int*   attn_mask = (const int*)  d_in[5];
    const float* w_qs_time = (const float*)d_in[6];
    const float* w_ks_time = (const float*)d_in[7];
    const float* w_qs_feat = (const float*)d_in[8];
    const float* w_ks_feat = (const float*)d_in[9];
    const float* w_vs      = (const float*)d_in[10];
    const float* w_fc      = (const float*)d_in[11];
    const float* ln_gamma  = (const float*)d_in[12];
    const float* ln_beta   = (const float*)d_in[13];
    float* out = (float*)d_out;

    __half *qt, *kt, *qf, *kf, *vvT, *prefc, *at16, *af16, *wh, *xh;
    float *preln, *afp;
    cudaGetSymbolAddress((void**)&qt,    g_qt);
    cudaGetSymbolAddress((void**)&kt,    g_kt);
    cudaGetSymbolAddress((void**)&qf,    g_qf);
    cudaGetSymbolAddress((void**)&kf,    g_kf);
    cudaGetSymbolAddress((void**)&vvT,   g_vvT);
    cudaGetSymbolAddress((void**)&prefc, g_prefc);
    cudaGetSymbolAddress((void**)&preln, g_preln);
    cudaGetSymbolAddress((void**)&afp,   g_afp);
    cudaGetSymbolAddress((void**)&at16,  g_at16);
    cudaGetSymbolAddress((void**)&af16,  g_af16);
    cudaGetSymbolAddress((void**)&wh,    g_wh);
    cudaGetSymbolAddress((void**)&xh,    g_xh);

    cudaFuncSetAttribute(proj_gemm,   cudaFuncAttributeMaxDynamicSharedMemorySize, SMEM_ALL);
    cudaFuncSetAttribute(fused_logits,cudaFuncAttributeMaxDynamicSharedMemorySize, SMEM_LOG);
    cudaFuncSetAttribute(attnv_fused, cudaFuncAttributeMaxDynamicSharedMemorySize, SMEM_FUSE);
    cudaFuncSetAttribute(fc_gemm,     cudaFuncAttributeMaxDynamicSharedMemorySize, SMEM_ALL);

    const float inv_temp = 1.0f / sqrtf((float)DKk);
    const int Z = Bz * Hh;  // 32
    dim3 blk(128);

    // 0) convert weights + inputs to fp16 (single launch)
    cvt_all_kernel<<<6 * 1024 + 5 * 4096, 256>>>(
        w_qs_time, w_ks_time, w_qs_feat, w_ks_feat, w_vs, w_fc,
        q_time, k_time, q_feature, k_feature, v, wh, xh);

    // 1) all projections (fp16 in/out; vv transposed)
    {
        dim3 grid(1, Nn / TBM, 5 * Z);
        proj_gemm<<<grid, blk, SMEM_ALL>>>(xh, wh, qt, kt, qf, kf, vvT);
    }

    float* at = out + AT_OFF;
    float* af = out + AF_OFF;

    // 2) time logits (A-resident strips) + feature split-K partials
    fused_logits<<<512 + 256, blk, SMEM_LOG>>>(qt, kt, qf, kf, at16, afp, inv_temp);

    // 3) both softmaxes in one launch (time part writes fp16 only)
    softmax_all_kernel<<<32768 + 4096, 128>>>(at16, attn_mask, afp, af, af16);

    // 4) prefc = (attn @ v) @ af, fused; echoes fp32 attn to d_out
    {
        dim3 grid(1, Nn / TBM, Z);
        attnv_fused<<<grid, blk, SMEM_FUSE>>>(at16, vvT, af16, prefc, at);
    }

    // 5) preln = prefc @ w_fc^T + v
    {
        dim3 grid(Dd / TBN, (Bz * Nn) / TBM, 1);
        fc_gemm<<<grid, blk, SMEM_ALL>>>(prefc, wh + 5u * 1048576u, preln, v);
    }

    // 6) LayerNorm
    layernorm_kernel<<<Bz * Nn, 256>>>(preln, out, ln_gamma, ln_beta);
}

// round 16
// speedup vs baseline: 1.0485x; 1.0485x over previous
#include <cuda_runtime.h>
#include <cuda_fp16.h>
#include <math.h>
#include <stdint.h>

// Problem constants
#define Bz   4
#define Nn   1024
#define Dd   1024
#define Hh   8
#define DKk  128
#define EPSf 1e-6f

static const long long AT_OFF  = (long long)Bz * Nn * Dd;                 // 4194304
static const long long AF_OFF  = AT_OFF + (long long)Bz * Hh * Nn * Nn;  // 37748736

#define PROJ_ELEMS ((long long)Bz * Hh * Nn * DKk)   // 4194304
__device__ __half g_qt[PROJ_ELEMS];
__device__ __half g_kt[PROJ_ELEMS];
__device__ __half g_qf[PROJ_ELEMS];
__device__ __half g_kf[PROJ_ELEMS];
__device__ __half g_vvT[PROJ_ELEMS];                  // [z][d][n] transposed
__device__ __half g_prefc[(long long)Bz * Nn * Dd];
__device__ float  g_preln[(long long)Bz * Nn * Dd];
__device__ float  g_afp[(long long)32 * 8 * DKk * DKk];     // split-K partials
__device__ __half g_at16[(long long)Bz * Hh * Nn * Nn];     // fp16 logits / attn
__device__ __half g_af16[(long long)32 * DKk * DKk];        // fp16 feat-attn copy
__device__ __half g_wh[6u * 1048576u];                      // fp16 weights
__device__ __half g_xh[5u * 4194304u];                      // fp16 inputs

__device__ __forceinline__ void cp_async16(void* dst, const void* src) {
    uint32_t s = (uint32_t)__cvta_generic_to_shared(dst);
    asm volatile("cp.async.cg.shared.global [%0], [%1], 16;" :: "r"(s), "l"(src));
}
__device__ __forceinline__ void cp_commit() {
    asm volatile("cp.async.commit_group;" ::: "memory");
}
__device__ __forceinline__ uint32_t pack_h2(const __half* lo, const __half* hi) {
    uint32_t u0 = *(const unsigned short*)lo;
    uint32_t u1 = *(const unsigned short*)hi;
    return u0 | (u1 << 16);
}
__device__ __forceinline__ uint32_t f2_to_h2(float x, float y) {
    __half2 h = __floats2half2_rn(x, y);
    return *(uint32_t*)&h;
}
__device__ __forceinline__ void ldsm_x4(uint32_t& r0, uint32_t& r1, uint32_t& r2, uint32_t& r3,
                                        uint32_t addr) {
    asm volatile("ldmatrix.sync.aligned.m8n8.x4.shared.b16 {%0,%1,%2,%3}, [%4];"
                 : "=r"(r0), "=r"(r1), "=r"(r2), "=r"(r3) : "r"(addr));
}

// One launch: convert 6 weight matrices + 5 input tensors to fp16.
__global__ void cvt_all_kernel(const float* w0, const float* w1, const float* w2,
                               const float* w3, const float* w4, const float* w5,
                               const float* x0, const float* x1, const float* x2,
                               const float* x3, const float* x4,
                               __half* wh, __half* xh) {
    int b = blockIdx.x;
    if (b < 6144) {
        const int t = b >> 10;
        const float* src;
        switch (t) {
            case 0: src = w0; break;  case 1: src = w1; break;
            case 2: src = w2; break;  case 3: src = w3; break;
            case 4: src = w4; break;  default: src = w5; break;
        }
        const long long e4 = (long long)(b & 1023) * 256 + threadIdx.x;
        float4 v = *(const float4*)(src + e4 * 4);
        *(uint2*)(wh + (long long)t * 1048576 + e4 * 4) =
            make_uint2(f2_to_h2(v.x, v.y), f2_to_h2(v.z, v.w));
    } else {
        b -= 6144;
        const int t = b >> 12;
        const float* src;
        switch (t) {
            case 0: src = x0; break;  case 1: src = x1; break;
            case 2: src = x2; break;  case 3: src = x3; break;
            default: src = x4; break;
        }
        const long long e4 = (long long)(b & 4095) * 256 + threadIdx.x;
        float4 v = *(const float4*)(src + e4 * 4);
        *(uint2*)(xh + (long long)t * 4194304 + e4 * 4) =
            make_uint2(f2_to_h2(v.x, v.y), f2_to_h2(v.z, v.w));
    }
}

// ---------------------------------------------------------------------------
// FP16 tensor-core GEMM body (3-stage cp.async). TBK=32, 128 thr = 4 warps
// (2x2), warp tile 64x64, mma m16n8k16 -> f32. ldmatrix for mode-0 operands.
//   AMODE 0: A [M,K] rm          AMODE 1: A [K,M] rm (A^T)
//   BMODE 0: B [N,K] rm (B^T)    BMODE 1: B [K,N] rm
//   CH 1: write C fp16 (else fp32 with optional residual R)
//   CT 1: write transposed fp16 C via smem staging
//   FUSE 1: after mainloop, multiply tile by af (Ct, K-major 128x128 fp16),
//           write fp16 product to Cb.
//   AECHO 1: echo each A smem tile as fp32 to Aecho (write-once streaming).
// ---------------------------------------------------------------------------
#define TBM 128
#define TBN 128
#define TBK 32
#define NSTG 3
#define SMEM_ALL 61440
#define SMEM_FUSE 70656

template<int AMODE, int BMODE, int CH, int CT, int FUSE, int AECHO>
__device__ __forceinline__ void gemm_f16(
    char* __restrict__ smem,
    const __half* __restrict__ Ab, const __half* __restrict__ Bb,
    void* __restrict__ Cb, const float* __restrict__ R,
    __half* __restrict__ Ct, int ldt,
    float* __restrict__ Aecho, int lde,
    int K, int lda, int ldb, int ldc, float alpha,
    int row0, int col0)
{
    constexpr int ASZB = (AMODE == 0) ? 128 * 40 * 2 : 32 * 136 * 2;
    constexpr int BSZB = (BMODE == 0) ? 128 * 40 * 2 : 32 * 136 * 2;

    char* sAb = smem;
    char* sBb = smem + NSTG * ASZB;

    const int tid  = threadIdx.x;
    const int lane = tid & 31;
    const int warp = tid >> 5;
    const int wm = (warp >> 1) * 64;
    const int wn = (warp & 1) * 64;
    const int g  = lane >> 2;
    const int t4 = lane & 3;
    const int lrow = lane & 7;
    const int lsel = lane >> 3;

    float acc[4][8][4];
    #pragma unroll
    for (int i = 0; i < 4; i++)
        #pragma unroll
        for (int j = 0; j < 8; j++)
            #pragma unroll
            for (int k = 0; k < 4; k++) acc[i][j][k] = 0.f;

    const int nIter = K / TBK;

    auto load_stage = [&](int buf, int k0) {
        if (AMODE == 0) {
            __half* dA = (__half*)(sAb + buf * ASZB);
            #pragma unroll
            for (int it = 0; it < 4; it++) {
                int f = tid + it * 128;
                int row = f >> 2, seg = (f & 3) * 8;
                cp_async16(&dA[row * 40 + seg], Ab + (long long)(row0 + row) * lda + k0 + seg);
            }
        } else {
            __half* dA = (__half*)(sAb + buf * ASZB);
            #pragma unroll
            for (int it = 0; it < 4; it++) {
                int f = tid + it * 128;
                int k = f >> 4, seg = (f & 15) * 8;
                cp_async16(&dA[k * 136 + seg], Ab + (long long)(k0 + k) * lda + row0 + seg);
            }
        }
        if (BMODE == 0) {
            __half* dB = (__half*)(sBb + buf * BSZB);
            #pragma unroll
            for (int it = 0; it < 4; it++) {
                int f = tid + it * 128;
                int row = f >> 2, seg = (f & 3) * 8;
                cp_async16(&dB[row * 40 + seg], Bb + (long long)(col0 + row) * ldb + k0 + seg);
            }
        } else {
            __half* dB = (__half*)(sBb + buf * BSZB);
            #pragma unroll
            for (int it = 0; it < 4; it++) {
                int f = tid + it * 128;
                int k = f >> 4, seg = (f & 15) * 8;
                cp_async16(&dB[k * 136 + seg], Bb + (long long)(k0 + k) * ldb + col0 + seg);
            }
        }
        cp_commit();
    };

    #pragma unroll
    for (int s = 0; s < NSTG; s++) load_stage(s, s * TBK);

    for (int it = 0; it < nIter; it++) {
        const int rem = nIter - 1 - it;
        if (rem >= 2)      asm volatile("cp.async.wait_group 2;" ::: "memory");
        else if (rem == 1) asm volatile("cp.async.wait_group 1;" ::: "memory");
        else               asm volatile("cp.async.wait_group 0;" ::: "memory");
        __syncthreads();

        const int cb = it % NSTG;
        const char* cAb = sAb + cb * ASZB;
        const char* cBb = sBb + cb * BSZB;
        const uint32_t sAu = (uint32_t)__cvta_generic_to_shared(cAb);
        const uint32_t sBu = (uint32_t)__cvta_generic_to_shared(cBb);

        #pragma unroll
        for (int kk = 0; kk < TBK; kk += 16) {
            uint32_t a[4][4], b[8][2];
            if (AMODE == 0) {
                #pragma unroll
                for (int mt = 0; mt < 4; mt++) {
                    int row = wm + mt * 16 + ((lsel & 1) << 3) + lrow;
                    int kc  = kk + ((lsel >> 1) << 3);
                    ldsm_x4(a[mt][0], a[mt][1], a[mt][2], a[mt][3],
                            sAu + (uint32_t)(row * 40 + kc) * 2u);
                }
            } else {
                const __half* cA = (const __half*)cAb;
                #pragma unroll
                for (int mt = 0; mt < 4; mt++) {
                    int mb = wm + mt * 16;
                    int kr = kk + 2 * t4;
                    a[mt][0] = pack_h2(&cA[kr * 136 + mb + g],       &cA[(kr + 1) * 136 + mb + g]);
                    a[mt][1] = pack_h2(&cA[kr * 136 + mb + g + 8],   &cA[(kr + 1) * 136 + mb + g + 8]);
                    a[mt][2] = pack_h2(&cA[(kr + 8) * 136 + mb + g], &cA[(kr + 9) * 136 + mb + g]);
                    a[mt][3] = pack_h2(&cA[(kr + 8) * 136 + mb + g + 8], &cA[(kr + 9) * 136 + mb + g + 8]);
                }
            }
            if (BMODE == 0) {
                #pragma unroll
                for (int p = 0; p < 4; p++) {
                    int row = wn + p * 16 + ((lsel >> 1) << 3) + lrow;
                    int kc  = kk + ((lsel & 1) << 3);
                    ldsm_x4(b[2 * p][0], b[2 * p][1], b[2 * p + 1][0], b[2 * p + 1][1],
                            sBu + (uint32_t)(row * 40 + kc) * 2u);
                }
            } else {
                const __half* cB = (const __half*)cBb;
                #pragma unroll
                for (int nt = 0; nt < 8; nt++) {
                    int nb = wn + nt * 8 + g;
                    int kr = kk + 2 * t4;
                    b[nt][0] = pack_h2(&cB[kr * 136 + nb],       &cB[(kr + 1) * 136 + nb]);
                    b[nt][1] = pack_h2(&cB[(kr + 8) * 136 + nb], &cB[(kr + 9) * 136 + nb]);
                }
            }
            #pragma unroll
            for (int mt = 0; mt < 4; mt++)
                #pragma unroll
                for (int nt = 0; nt < 8; nt++) {
                    asm volatile(
                        "mma.sync.aligned.m16n8k16.row.col.f32.f16.f16.f32 "
                        "{%0,%1,%2,%3}, {%4,%5,%6,%7}, {%8,%9}, {%0,%1,%2,%3};"
                        : "+f"(acc[mt][nt][0]), "+f"(acc[mt][nt][1]),
                          "+f"(acc[mt][nt][2]), "+f"(acc[mt][nt][3])
                        : "r"(a[mt][0]), "r"(a[mt][1]), "r"(a[mt][2]), "r"(a[mt][3]),
                          "r"(b[nt][0]), "r"(b[nt][1]));
                }
        }
        if (AECHO && AMODE == 0) {
            const __half* cA2 = (const __half*)cAb;
            const int k0 = it * TBK;
            #pragma unroll
            for (int i = 0; i < 4; i++) {
                int f = tid + i * 128;
                int row = f >> 2, seg = (f & 3) * 8;
                const __half* src = &cA2[row * 40 + seg];
                float4 lo = make_float4(__half2float(src[0]), __half2float(src[1]),
                                        __half2float(src[2]), __half2float(src[3]));
                float4 hi = make_float4(__half2float(src[4]), __half2float(src[5]),
                                        __half2float(src[6]), __half2float(src[7]));
                float* dst = Aecho + (long long)(row0 + row) * lde + k0 + seg;
                __stwt((float4*)dst, lo);
                __stwt((float4*)(dst + 4), hi);
            }
        }
        __syncthreads();
        if (it + NSTG < nIter) load_stage(cb, (it + NSTG) * TBK);
    }

    if (FUSE) {
        __half* stA = (__half*)smem;                 // [128][136]
        __half* stB = (__half*)(smem + 34816);       // [128][136]
        #pragma unroll
        for (int i = 0; i < 16; i++) {
            int f = tid + i * 128;
            int row = f >> 4, seg = (f & 15) * 8;
            cp_async16(&stB[row * 136 + seg], Ct + row * 128 + seg);
        }
        cp_commit();
        #pragma unroll
        for (int mt = 0; mt < 4; mt++) {
            int rl = wm + mt * 16 + g;
            #pragma unroll
            for (int nt = 0; nt < 8; nt++) {
                int c = wn + nt * 8 + t4 * 2;
                *(uint32_t*)&stA[rl * 136 + c]       = f2_to_h2(acc[mt][nt][0], acc[mt][nt][1]);
                *(uint32_t*)&stA[(rl + 8) * 136 + c] = f2_to_h2(acc[mt][nt][2], acc[mt][nt][3]);
            }
        }
        asm volatile("cp.async.wait_group 0;" ::: "memory");
        __syncthreads();

        float ac2[4][8][4];
        #pragma unroll
        for (int i = 0; i < 4; i++)
            #pragma unroll
            for (int j = 0; j < 8; j++)
                #pragma unroll
                for (int k = 0; k < 4; k++) ac2[i][j][k] = 0.f;

        #pragma unroll
        for (int kk = 0; kk < 128; kk += 16) {
            uint32_t a[4][4], b[8][2];
            #pragma unroll
            for (int mt = 0; mt < 4; mt++) {
                int mb = wm + mt * 16 + g;
                a[mt][0] = *(const uint32_t*)&stA[mb * 136 + kk + 2 * t4];
                a[mt][1] = *(const uint32_t*)&stA[(mb + 8) * 136 + kk + 2 * t4];
                a[mt][2] = *(const uint32_t*)&stA[mb * 136 + kk + 2 * t4 + 8];
                a[mt][3] = *(const uint32_t*)&stA[(mb + 8) * 136 + kk + 2 * t4 + 8];
            }
            #pragma unroll
            for (int nt = 0; nt < 8; nt++) {
                int nb = wn + nt * 8 + g;
                int kr = kk + 2 * t4;
                b[nt][0] = pack_h2(&stB[kr * 136 + nb],       &stB[(kr + 1) * 136 + nb]);
                b[nt][1] = pack_h2(&stB[(kr + 8) * 136 + nb], &stB[(kr + 9) * 136 + nb]);
            }
            #pragma unroll
            for (int mt = 0; mt < 4; mt++)
                #pragma unroll
                for (int nt = 0; nt < 8; nt++) {
                    asm volatile(
                        "mma.sync.aligned.m16n8k16.row.col.f32.f16.f16.f32 "
                        "{%0,%1,%2,%3}, {%4,%5,%6,%7}, {%8,%9}, {%0,%1,%2,%3};"
                        : "+f"(ac2[mt][nt][0]), "+f"(ac2[mt][nt][1]),
                          "+f"(ac2[mt][nt][2]), "+f"(ac2[mt][nt][3])
                        : "r"(a[mt][0]), "r"(a[mt][1]), "r"(a[mt][2]), "r"(a[mt][3]),
                          "r"(b[nt][0]), "r"(b[nt][1]));
                }
        }
        __half* Ch = (__half*)Cb;
        #pragma unroll
        for (int mt = 0; mt < 4; mt++) {
            int r0g = row0 + wm + mt * 16 + g;
            #pragma unroll
            for (int nt = 0; nt < 8; nt++) {
                int c0g = wn + nt * 8 + t4 * 2;
                *(uint32_t*)(Ch + (long long)r0g * ldc + c0g)       = f2_to_h2(ac2[mt][nt][0], ac2[mt][nt][1]);
                *(uint32_t*)(Ch + (long long)(r0g + 8) * ldc + c0g) = f2_to_h2(ac2[mt][nt][2], ac2[mt][nt][3]);
            }
        }
        return;
    }

    if (CT) {
        __half* st = (__half*)smem;
        #pragma unroll
        for (int mt = 0; mt < 4; mt++) {
            int rl = wm + mt * 16 + g;
            #pragma unroll
            for (int nt = 0; nt < 8; nt++) {
                int c = wn + nt * 8 + t4 * 2;
                st[c * 136 + rl]            = __float2half_rn(acc[mt][nt][0] * alpha);
                st[(c + 1) * 136 + rl]      = __float2half_rn(acc[mt][nt][1] * alpha);
                st[c * 136 + rl + 8]        = __float2half_rn(acc[mt][nt][2] * alpha);
                st[(c + 1) * 136 + rl + 8]  = __float2half_rn(acc[mt][nt][3] * alpha);
            }
        }
        __syncthreads();
        #pragma unroll
        for (int it2 = 0; it2 < 16; it2++) {
            int i = tid + it2 * 128;
            int d = i >> 4, seg = (i & 15) * 8;
            *(uint4*)(Ct + (long long)d * ldt + row0 + seg) = *(const uint4*)&st[d * 136 + seg];
        }
        return;
    }

    #pragma unroll
    for (int mt = 0; mt < 4; mt++) {
        int r0g = row0 + wm + mt * 16 + g;
        #pragma unroll
        for (int nt = 0; nt < 8; nt++) {
            int c0g = col0 + wn + nt * 8 + t4 * 2;
            float v0 = acc[mt][nt][0] * alpha;
            float v1 = acc[mt][nt][1] * alpha;
            float v2 = acc[mt][nt][2] * alpha;
            float v3 = acc[mt][nt][3] * alpha;
            if (CH) {
                __half* Ch = (__half*)Cb;
                *(uint32_t*)(Ch + (long long)r0g * ldc + c0g)       = f2_to_h2(v0, v1);
                *(uint32_t*)(Ch + (long long)(r0g + 8) * ldc + c0g) = f2_to_h2(v2, v3);
            } else {
                float* Cf = (float*)Cb;
                if (R) {
                    v0 += R[(long long)r0g * ldc + c0g];
                    v1 += R[(long long)r0g * ldc + c0g + 1];
                    v2 += R[(long long)(r0g + 8) * ldc + c0g];
                    v3 += R[(long long)(r0g + 8) * ldc + c0g + 1];
                }
                *(float2*)(Cf + (long long)r0g * ldc + c0g)       = make_float2(v0, v1);
                *(float2*)(Cf + (long long)(r0g + 8) * ldc + c0g) = make_float2(v2, v3);
            }
        }
    }
}

// ---------------------------------------------------------------------------
// Kernels
// ---------------------------------------------------------------------------

// All 5 projections, fp16 in/out. z in [0,160): p = z/32, zz = z%32 = (b,h).
__global__ void __launch_bounds__(128, 3)
proj_gemm(const __half* __restrict__ xh, const __half* __restrict__ wh,
          __half* qt, __half* kt, __half* qf, __half* kf, __half* vvT) {
    extern __shared__ char dynsmem[];
    const int z = blockIdx.z;
    const int p = z >> 5, zz = z & 31;
    const __half* Ab = xh + (long long)p * 4194304 + (long long)(zz >> 3) * Nn * Dd;
    const __half* Bb = wh + (long long)p * 1048576 + (long long)(zz & 7) * DKk * Dd;
    const int row0 = blockIdx.y * TBM;
    if (p == 4) {
        gemm_f16<0, 0, 1, 1, 0, 0>(dynsmem, Ab, Bb, nullptr, nullptr,
                                   vvT + (long long)zz * DKk * Nn, Nn, nullptr, 0,
                                   Dd, Dd, Dd, DKk, 1.0f, row0, 0);
    } else {
        __half* C;
        switch (p) {
            case 0: C = qt; break;  case 1: C = kt; break;
            case 2: C = qf; break;  default: C = kf; break;
        }
        gemm_f16<0, 0, 1, 0, 0, 0>(dynsmem, Ab, Bb,
                                   C + (long long)zz * Nn * DKk, nullptr, nullptr, 0, nullptr, 0,
                                   Dd, Dd, Dd, DKk, 1.0f, row0, 0);
    }
}

// feature split-K partials (blocks 0..255, scheduled first) +
// time logits (blocks 256..2303, fp16 out, scaled).
__global__ void __launch_bounds__(128, 3)
fused_logits(const __half* __restrict__ qt, const __half* __restrict__ kt,
             const __half* __restrict__ qf, const __half* __restrict__ kf,
             __half* __restrict__ at16, float* __restrict__ afp, float alpha) {
    extern __shared__ char dynsmem[];
    const int bx = blockIdx.x;
    if (bx < 256) {
        const int e = bx;
        const int z = e >> 3, sub = e & 7;
        const long long base = (long long)z * Nn * DKk + (long long)sub * 128 * DKk;
        gemm_f16<1, 1, 0, 0, 0, 0>(dynsmem,
                        qf + base, kf + base,
                        afp + (long long)e * DKk * DKk, nullptr, nullptr, 0, nullptr, 0,
                        128, DKk, DKk, DKk, alpha, 0, 0);
    } else {
        const int t = bx - 256;
        const int z = t >> 6, rem = t & 63;
        gemm_f16<0, 0, 1, 0, 0, 0>(dynsmem,
                        qt + (long long)z * Nn * DKk,
                        kt + (long long)z * Nn * DKk,
                        at16 + (long long)z * Nn * Nn, nullptr, nullptr, 0, nullptr, 0,
                        DKk, DKk, DKk, Nn, alpha,
                        (rem >> 3) * TBM, (rem & 7) * TBN);
    }
}

// fused: prefc tile = (at16 @ vvT^T) @ af16, written to prefc; echoes attn fp32.
__global__ void __launch_bounds__(128, 3)
attnv_fused(const __half* __restrict__ at16, const __half* __restrict__ vvT,
            const __half* __restrict__ af16, __half* __restrict__ prefc,
            float* __restrict__ at_out) {
    extern __shared__ char dynsmem[];
    const int z = blockIdx.z;
    gemm_f16<0, 0, 1, 0, 1, 1>(dynsmem,
                    at16 + (long long)z * Nn * Nn,
                    vvT + (long long)z * DKk * Nn,
                    prefc + (long long)(z >> 3) * Nn * Dd + (z & 7) * DKk,
                    nullptr,
                    (__half*)(af16 + (long long)z * DKk * DKk), 0,
                    at_out + (long long)z * Nn * Nn, Nn,
                    Nn, Nn, Nn, Dd, 1.0f, blockIdx.y * TBM, 0);
}

// preln = prefc @ w_fc^T + v
__global__ void __launch_bounds__(128, 3)
fc_gemm(const __half* __restrict__ prefc, const __half* __restrict__ wfc,
        float* __restrict__ preln, const float* __restrict__ v) {
    extern __shared__ char dynsmem[];
    gemm_f16<0, 0, 0, 0, 0, 0>(dynsmem, prefc, wfc, preln, v, nullptr, 0, nullptr, 0,
                    Dd, Dd, Dd, Dd, 1.0f,
                    blockIdx.y * TBM, blockIdx.x * TBN);
}

// ---------------------------------------------------------------------------
__device__ __forceinline__ float block_reduce(float v, bool is_max) {
    __shared__ float sh[32];
    int lane = threadIdx.x & 31, w = threadIdx.x >> 5;
    #pragma unroll
    for (int o = 16; o > 0; o >>= 1) {
        float o2 = __shfl_xor_sync(0xffffffff, v, o);
        v = is_max ? fmaxf(v, o2) : v + o2;
    }
    if (lane == 0) sh[w] = v;
    __syncthreads();
    int nw = (blockDim.x + 31) >> 5;
    v = (lane < nw) ? sh[lane] : (is_max ? -3.4e38f : 0.f);
    if (w == 0) {
        #pragma unroll
        for (int o = 16; o > 0; o >>= 1) {
            float o2 = __shfl_xor_sync(0xffffffff, v, o);
            v = is_max ? fmaxf(v, o2) : v + o2;
        }
        if (lane == 0) sh[0] = v;
    }
    __syncthreads();
    v = sh[0];
    __syncthreads();
    return v;
}

// Merged softmax launch. Time rows: no max-subtraction (logits bounded);
// masked lanes contribute 0. Writes normalized fp16 in place.
__global__ void softmax_all_kernel(__half* __restrict__ at16,
                                   const int* __restrict__ mask,
                                   const float* __restrict__ afp,
                                   float* __restrict__ S,
                                   __half* __restrict__ S16) {
    if (blockIdx.x < 32768) {
        const int r = blockIdx.x;
        const int b = r / (Hh * Nn);
        const int n = r % Nn;
        __half* row16 = at16 + (long long)r * Nn;
        const int* mrow = mask + ((long long)b * Nn + n) * Nn;
        const int j0 = threadIdx.x * 8;

        uint4 lv = *(const uint4*)(row16 + j0);
        __half2 h0 = *(__half2*)&lv.x, h1 = *(__half2*)&lv.y;
        __half2 h2 = *(__half2*)&lv.z, h3 = *(__half2*)&lv.w;
        int4 m0 = __ldg((const int4*)(mrow + j0));
        int4 m1 = __ldg((const int4*)(mrow + j0 + 4));
        float x[8];
        x[0] = m0.x == 0 ? 0.f : __expf(__low2float(h0));
        x[1] = m0.y == 0 ? 0.f : __expf(__high2float(h0));
        x[2] = m0.z == 0 ? 0.f : __expf(__low2float(h1));
        x[3] = m0.w == 0 ? 0.f : __expf(__high2float(h1));
        x[4] = m1.x == 0 ? 0.f : __expf(__low2float(h2));
        x[5] = m1.y == 0 ? 0.f : __expf(__high2float(h2));
        x[6] = m1.z == 0 ? 0.f : __expf(__low2float(h3));
        x[7] = m1.w == 0 ? 0.f : __expf(__high2float(h3));
        float s = 0.f;
        #pragma unroll
        for (int i = 0; i < 8; i++) s += x[i];
        s = block_reduce(s, false);
        float inv = 1.f / s;
        #pragma unroll
        for (int i = 0; i < 8; i++) x[i] *= inv;
        uint4 ov = make_uint4(f2_to_h2(x[0], x[1]), f2_to_h2(x[2], x[3]),
                              f2_to_h2(x[4], x[5]), f2_to_h2(x[6], x[7]));
        *(uint4*)(row16 + j0) = ov;
    } else {
        const int e = blockIdx.x - 32768;
        const int z = e >> 7;
        const int row = e & 127;
        const int t = threadIdx.x;
        float v = 0.f;
        #pragma unroll
        for (int s8 = 0; s8 < 8; s8++)
            v += afp[(((long long)z * 8 + s8) * DKk + row) * DKk + t];
        float mx = block_reduce(v, true);
        float ex = __expf(v - mx);
        float s = block_reduce(ex, false);
        float o = ex / s;
        __stwt(&S[((long long)z * DKk + row) * DKk + t], o);
        S16[((long long)z * DKk + row) * DKk + t] = __float2half_rn(o);
    }
}

__global__ void layernorm_kernel(const float* __restrict__ X, float* __restrict__ O,
                                 const float* __restrict__ gamma, const float* __restrict__ beta) {
    const int r = blockIdx.x;
    const float* row = X + (long long)r * Dd;
    float* orow = O + (long long)r * Dd;
    const int j0 = threadIdx.x * 4;
    float4 xv = *(const float4*)(row + j0);
    float x[4] = {xv.x, xv.y, xv.z, xv.w};
    float s = x[0] + x[1] + x[2] + x[3];
    float s2 = x[0]*x[0] + x[1]*x[1] + x[2]*x[2] + x[3]*x[3];
    s = block_reduce(s, false);
    s2 = block_reduce(s2, false);
    float mean = s * (1.f / Dd);
    float var = s2 * (1.f / Dd) - mean * mean;
    float inv = rsqrtf(var + EPSf);
    float4 gv = *(const float4*)(gamma + j0);
    float4 bv = *(const float4*)(beta + j0);
    __stwt((float4*)(orow + j0),
           make_float4((x[0] - mean) * inv * gv.x + bv.x,
                       (x[1] - mean) * inv * gv.y + bv.y,
                       (x[2] - mean) * inv * gv.z + bv.z,
                       (x[3] - mean) * inv * gv.w + bv.w));
}

// ---------------------------------------------------------------------------
extern "C" void kernel_launch(void* const* d_in, const int* in_sizes, int n_in,
                              void* d_out, int out_size) {
    const float* q_time    = (const float*)d_in[0];
    const float* k_time    = (const float*)d_in[1];
    const float* q_feature = (const float*)d_in[2];
    const float* k_feature = (const float*)d_in[3];
    const float* v         = (const float*)d_in[4];
    const int*   attn_mask = (const int*)  d_in[5];
    const float* w_qs_time = (const float*)d_in[6];
    const float* w_ks_time = (const float*)d_in[7];
    const float* w_qs_feat = (const float*)d_in[8];
    const float* w_ks_feat = (const float*)d_in[9];
    const float* w_vs      = (const float*)d_in[10];
    const float* w_fc      = (const float*)d_in[11];
    const float* ln_gamma  = (const float*)d_in[12];
    const float* ln_beta   = (const float*)d_in[13];
    float* out = (float*)d_out;

    __half *qt, *kt, *qf, *kf, *vvT, *prefc, *at16, *af16, *wh, *xh;
    float *preln, *afp;
    cudaGetSymbolAddress((void**)&qt,    g_qt);
    cudaGetSymbolAddress((void**)&kt,    g_kt);
    cudaGetSymbolAddress((void**)&qf,    g_qf);
    cudaGetSymbolAddress((void**)&kf,    g_kf);
    cudaGetSymbolAddress((void**)&vvT,   g_vvT);
    cudaGetSymbolAddress((void**)&prefc, g_prefc);
    cudaGetSymbolAddress((void**)&preln, g_preln);
    cudaGetSymbolAddress((void**)&afp,   g_afp);
    cudaGetSymbolAddress((void**)&at16,  g_at16);
    cudaGetSymbolAddress((void**)&af16,  g_af16);
    cudaGetSymbolAddress((void**)&wh,    g_wh);
    cudaGetSymbolAddress((void**)&xh,    g_xh);

    cudaFuncSetAttribute(proj_gemm,   cudaFuncAttributeMaxDynamicSharedMemorySize, SMEM_ALL);
    cudaFuncSetAttribute(fused_logits,cudaFuncAttributeMaxDynamicSharedMemorySize, SMEM_ALL);
    cudaFuncSetAttribute(attnv_fused, cudaFuncAttributeMaxDynamicSharedMemorySize, SMEM_FUSE);
    cudaFuncSetAttribute(fc_gemm,     cudaFuncAttributeMaxDynamicSharedMemorySize, SMEM_ALL);

    const float inv_temp = 1.0f / sqrtf((float)DKk);
    const int Z = Bz * Hh;  // 32
    dim3 blk(128);

    // 0) convert weights + inputs to fp16 (single launch)
    cvt_all_kernel<<<6 * 1024 + 5 * 4096, 256>>>(
        w_qs_time, w_ks_time, w_qs_feat, w_ks_feat, w_vs, w_fc,
        q_time, k_time, q_feature, k_feature, v, wh, xh);

    // 1) all projections (fp16 in/out; vv transposed)
    {
        dim3 grid(1, Nn / TBM, 5 * Z);
        proj_gemm<<<grid, blk, SMEM_ALL>>>(xh, wh, qt, kt, qf, kf, vvT);
    }

    float* at = out + AT_OFF;
    float* af = out + AF_OFF;

    // 2) feature split-K partials (first) + time logits (fp16)
    fused_logits<<<256 + 2048, blk, SMEM_ALL>>>(qt, kt, qf, kf, at16, afp, inv_temp);

    // 3) both softmaxes in one launch (time part writes fp16 only)
    softmax_all_kernel<<<32768 + 4096, 128>>>(at16, attn_mask, afp, af, af16);

    // 4) prefc = (attn @ v) @ af, fused; echoes fp32 attn to d_out
    {
        dim3 grid(1, Nn / TBM, Z);
        attnv_fused<<<grid, blk, SMEM_FUSE>>>(at16, vvT, af16, prefc, at);
    }

    // 5) preln = prefc @ w_fc^T + v
    {
        dim3 grid(Dd / TBN, (Bz * Nn) / TBM, 1);
        fc_gemm<<<grid, blk, SMEM_ALL>>>(prefc, wh + 5u * 1048576u, preln, v);
    }

    // 6) LayerNorm
    layernorm_kernel<<<Bz * Nn, 256>>>(preln, out, ln_gamma, ln_beta);
}

// round 17
// speedup vs baseline: 1.0640x; 1.0148x over previous
#include <cuda_runtime.h>
#include <cuda_fp16.h>
#include <math.h>
#include <stdint.h>

// Problem constants
#define Bz   4
#define Nn   1024
#define Dd   1024
#define Hh   8
#define DKk  128
#define EPSf 1e-6f

static const long long AT_OFF  = (long long)Bz * Nn * Dd;                 // 4194304
static const long long AF_OFF  = AT_OFF + (long long)Bz * Hh * Nn * Nn;  // 37748736

#define PROJ_ELEMS ((long long)Bz * Hh * Nn * DKk)   // 4194304
__device__ __half g_qt[PROJ_ELEMS];
__device__ __half g_kt[PROJ_ELEMS];
__device__ __half g_qf[PROJ_ELEMS];
__device__ __half g_kf[PROJ_ELEMS];
__device__ __half g_vvT[PROJ_ELEMS];                  // [z][d][n] transposed
__device__ __half g_prefc[(long long)Bz * Nn * Dd];
__device__ float  g_preln[(long long)Bz * Nn * Dd];
__device__ float  g_afp[(long long)32 * 8 * DKk * DKk];     // split-K partials
__device__ __half g_at16[(long long)Bz * Hh * Nn * Nn];     // fp16 logits / attn
__device__ __half g_af16[(long long)32 * DKk * DKk];        // fp16 feat-attn copy
__device__ __half g_wh[6u * 1048576u];                      // fp16 weights
__device__ __half g_xh[5u * 4194304u];                      // fp16 inputs

__device__ __forceinline__ void cp_async16(void* dst, const void* src) {
    uint32_t s = (uint32_t)__cvta_generic_to_shared(dst);
    asm volatile("cp.async.cg.shared.global [%0], [%1], 16;" :: "r"(s), "l"(src));
}
__device__ __forceinline__ void cp_commit() {
    asm volatile("cp.async.commit_group;" ::: "memory");
}
__device__ __forceinline__ uint32_t pack_h2(const __half* lo, const __half* hi) {
    uint32_t u0 = *(const unsigned short*)lo;
    uint32_t u1 = *(const unsigned short*)hi;
    return u0 | (u1 << 16);
}
__device__ __forceinline__ uint32_t f2_to_h2(float x, float y) {
    __half2 h = __floats2half2_rn(x, y);
    return *(uint32_t*)&h;
}
__device__ __forceinline__ void ldsm_x4(uint32_t& r0, uint32_t& r1, uint32_t& r2, uint32_t& r3,
                                        uint32_t addr) {
    asm volatile("ldmatrix.sync.aligned.m8n8.x4.shared.b16 {%0,%1,%2,%3}, [%4];"
                 : "=r"(r0), "=r"(r1), "=r"(r2), "=r"(r3) : "r"(addr));
}

// One launch: convert 6 weight matrices + 5 input tensors to fp16.
__global__ void cvt_all_kernel(const float* w0, const float* w1, const float* w2,
                               const float* w3, const float* w4, const float* w5,
                               const float* x0, const float* x1, const float* x2,
                               const float* x3, const float* x4,
                               __half* wh, __half* xh) {
    int b = blockIdx.x;
    if (b < 6144) {
        const int t = b >> 10;
        const float* src;
        switch (t) {
            case 0: src = w0; break;  case 1: src = w1; break;
            case 2: src = w2; break;  case 3: src = w3; break;
            case 4: src = w4; break;  default: src = w5; break;
        }
        const long long e4 = (long long)(b & 1023) * 256 + threadIdx.x;
        float4 v = *(const float4*)(src + e4 * 4);
        *(uint2*)(wh + (long long)t * 1048576 + e4 * 4) =
            make_uint2(f2_to_h2(v.x, v.y), f2_to_h2(v.z, v.w));
    } else {
        b -= 6144;
        const int t = b >> 12;
        const float* src;
        switch (t) {
            case 0: src = x0; break;  case 1: src = x1; break;
            case 2: src = x2; break;  case 3: src = x3; break;
            default: src = x4; break;
        }
        const long long e4 = (long long)(b & 4095) * 256 + threadIdx.x;
        float4 v = *(const float4*)(src + e4 * 4);
        *(uint2*)(xh + (long long)t * 4194304 + e4 * 4) =
            make_uint2(f2_to_h2(v.x, v.y), f2_to_h2(v.z, v.w));
    }
}

// ---------------------------------------------------------------------------
// FP16 tensor-core GEMM body. Template TBK (32 or 64), NSTG stages.
// 128 thr = 4 warps (2x2), warp tile 64x64, mma m16n8k16 -> f32.
// ldmatrix for mode-0 operands (stride TBK+8 halfs, conflict-free).
//   AMODE 0: A [M,K] rm          AMODE 1: A [K,M] rm (A^T)
//   BMODE 0: B [N,K] rm (B^T)    BMODE 1: B [K,N] rm
//   CH 1: write C fp16 (else fp32 with optional residual R)
//   CT 1: write transposed fp16 C via smem staging
//   FUSE 1: after mainloop, multiply tile by af (Ct, K-major 128x128 fp16)
//   AECHO 1: echo each A smem tile as fp32 to Aecho (write-once streaming)
// ---------------------------------------------------------------------------
#define TBM 128
#define TBN 128
#define SMEM_ALL  61440     // TBK=32 / NSTG=3 path
#define SMEM_BIG  73728     // TBK=64 / NSTG=2 path (also covers FUSE epilogue)

template<int TBK, int NSTG, int AMODE, int BMODE, int CH, int CT, int FUSE, int AECHO>
__device__ __forceinline__ void gemm_f16(
    char* __restrict__ smem,
    const __half* __restrict__ Ab, const __half* __restrict__ Bb,
    void* __restrict__ Cb, const float* __restrict__ R,
    __half* __restrict__ Ct, int ldt,
    float* __restrict__ Aecho, int lde,
    int K, int lda, int ldb, int ldc, float alpha,
    int row0, int col0)
{
    constexpr int AST  = TBK + 8;                       // mode-0 stride (halfs)
    constexpr int ASZB = (AMODE == 0) ? 128 * AST * 2 : TBK * 136 * 2;
    constexpr int BSZB = (BMODE == 0) ? 128 * AST * 2 : TBK * 136 * 2;
    constexpr int NLD0 = (128 * TBK) / (8 * 128);       // cp16 per thread, mode 0
    constexpr int NLD1 = (TBK * 128) / (8 * 128);       // cp16 per thread, mode 1

    char* sAb = smem;
    char* sBb = smem + NSTG * ASZB;

    const int tid  = threadIdx.x;
    const int lane = tid & 31;
    const int warp = tid >> 5;
    const int wm = (warp >> 1) * 64;
    const int wn = (warp & 1) * 64;
    const int g  = lane >> 2;
    const int t4 = lane & 3;
    const int lrow = lane & 7;
    const int lsel = lane >> 3;

    float acc[4][8][4];
    #pragma unroll
    for (int i = 0; i < 4; i++)
        #pragma unroll
        for (int j = 0; j < 8; j++)
            #pragma unroll
            for (int k = 0; k < 4; k++) acc[i][j][k] = 0.f;

    const int nIter = K / TBK;

    auto load_stage = [&](int buf, int k0) {
        if (AMODE == 0) {
            __half* dA = (__half*)(sAb + buf * ASZB);
            #pragma unroll
            for (int it = 0; it < NLD0; it++) {
                int f = tid + it * 128;
                int row = f / (TBK / 8), seg = (f % (TBK / 8)) * 8;
                cp_async16(&dA[row * AST + seg], Ab + (long long)(row0 + row) * lda + k0 + seg);
            }
        } else {
            __half* dA = (__half*)(sAb + buf * ASZB);
            #pragma unroll
            for (int it = 0; it < NLD1; it++) {
                int f = tid + it * 128;
                int k = f >> 4, seg = (f & 15) * 8;
                cp_async16(&dA[k * 136 + seg], Ab + (long long)(k0 + k) * lda + row0 + seg);
            }
        }
        if (BMODE == 0) {
            __half* dB = (__half*)(sBb + buf * BSZB);
            #pragma unroll
            for (int it = 0; it < NLD0; it++) {
                int f = tid + it * 128;
                int row = f / (TBK / 8), seg = (f % (TBK / 8)) * 8;
                cp_async16(&dB[row * AST + seg], Bb + (long long)(col0 + row) * ldb + k0 + seg);
            }
        } else {
            __half* dB = (__half*)(sBb + buf * BSZB);
            #pragma unroll
            for (int it = 0; it < NLD1; it++) {
                int f = tid + it * 128;
                int k = f >> 4, seg = (f & 15) * 8;
                cp_async16(&dB[k * 136 + seg], Bb + (long long)(k0 + k) * ldb + col0 + seg);
            }
        }
        cp_commit();
    };

    #pragma unroll
    for (int s = 0; s < NSTG; s++) load_stage(s, s * TBK);

    for (int it = 0; it < nIter; it++) {
        const int rem = nIter - 1 - it;
        if (NSTG == 3) {
            if (rem >= 2)      asm volatile("cp.async.wait_group 2;" ::: "memory");
            else if (rem == 1) asm volatile("cp.async.wait_group 1;" ::: "memory");
            else               asm volatile("cp.async.wait_group 0;" ::: "memory");
        } else {
            if (rem >= 1)      asm volatile("cp.async.wait_group 1;" ::: "memory");
            else               asm volatile("cp.async.wait_group 0;" ::: "memory");
        }
        __syncthreads();

        const int cb = it % NSTG;
        const char* cAb = sAb + cb * ASZB;
        const char* cBb = sBb + cb * BSZB;
        const uint32_t sAu = (uint32_t)__cvta_generic_to_shared(cAb);
        const uint32_t sBu = (uint32_t)__cvta_generic_to_shared(cBb);

        #pragma unroll
        for (int kk = 0; kk < TBK; kk += 16) {
            uint32_t a[4][4], b[8][2];
            if (AMODE == 0) {
                #pragma unroll
                for (int mt = 0; mt < 4; mt++) {
                    int row = wm + mt * 16 + ((lsel & 1) << 3) + lrow;
                    int kc  = kk + ((lsel >> 1) << 3);
                    ldsm_x4(a[mt][0], a[mt][1], a[mt][2], a[mt][3],
                            sAu + (uint32_t)(row * AST + kc) * 2u);
                }
            } else {
                const __half* cA = (const __half*)cAb;
                #pragma unroll
                for (int mt = 0; mt < 4; mt++) {
                    int mb = wm + mt * 16;
                    int kr = kk + 2 * t4;
                    a[mt][0] = pack_h2(&cA[kr * 136 + mb + g],       &cA[(kr + 1) * 136 + mb + g]);
                    a[mt][1] = pack_h2(&cA[kr * 136 + mb + g + 8],   &cA[(kr + 1) * 136 + mb + g + 8]);
                    a[mt][2] = pack_h2(&cA[(kr + 8) * 136 + mb + g], &cA[(kr + 9) * 136 + mb + g]);
                    a[mt][3] = pack_h2(&cA[(kr + 8) * 136 + mb + g + 8], &cA[(kr + 9) * 136 + mb + g + 8]);
                }
            }
            if (BMODE == 0) {
                #pragma unroll
                for (int p = 0; p < 4; p++) {
                    int row = wn + p * 16 + ((lsel >> 1) << 3) + lrow;
                    int kc  = kk + ((lsel & 1) << 3);
                    ldsm_x4(b[2 * p][0], b[2 * p][1], b[2 * p + 1][0], b[2 * p + 1][1],
                            sBu + (uint32_t)(row * AST + kc) * 2u);
                }
            } else {
                const __half* cB = (const __half*)cBb;
                #pragma unroll
                for (int nt = 0; nt < 8; nt++) {
                    int nb = wn + nt * 8 + g;
                    int kr = kk + 2 * t4;
                    b[nt][0] = pack_h2(&cB[kr * 136 + nb],       &cB[(kr + 1) * 136 + nb]);
                    b[nt][1] = pack_h2(&cB[(kr + 8) * 136 + nb], &cB[(kr + 9) * 136 + nb]);
                }
            }
            #pragma unroll
            for (int mt = 0; mt < 4; mt++)
                #pragma unroll
                for (int nt = 0; nt < 8; nt++) {
                    asm volatile(
                        "mma.sync.aligned.m16n8k16.row.col.f32.f16.f16.f32 "
                        "{%0,%1,%2,%3}, {%4,%5,%6,%7}, {%8,%9}, {%0,%1,%2,%3};"
                        : "+f"(acc[mt][nt][0]), "+f"(acc[mt][nt][1]),
                          "+f"(acc[mt][nt][2]), "+f"(acc[mt][nt][3])
                        : "r"(a[mt][0]), "r"(a[mt][1]), "r"(a[mt][2]), "r"(a[mt][3]),
                          "r"(b[nt][0]), "r"(b[nt][1]));
                }
        }
        if (AECHO && AMODE == 0) {
            const __half* cA2 = (const __half*)cAb;
            const int k0 = it * TBK;
            #pragma unroll
            for (int i = 0; i < NLD0; i++) {
                int f = tid + i * 128;
                int row = f / (TBK / 8), seg = (f % (TBK / 8)) * 8;
                const __half* src = &cA2[row * AST + seg];
                float4 lo = make_float4(__half2float(src[0]), __half2float(src[1]),
                                        __half2float(src[2]), __half2float(src[3]));
                float4 hi = make_float4(__half2float(src[4]), __half2float(src[5]),
                                        __half2float(src[6]), __half2float(src[7]));
                float* dst = Aecho + (long long)(row0 + row) * lde + k0 + seg;
                __stwt((float4*)dst, lo);
                __stwt((float4*)(dst + 4), hi);
            }
        }
        __syncthreads();
        if (it + NSTG < nIter) load_stage(cb, (it + NSTG) * TBK);
    }

    if (FUSE) {
        __half* stA = (__half*)smem;                 // [128][136]
        __half* stB = (__half*)(smem + 34816);       // [128][136]
        #pragma unroll
        for (int i = 0; i < 16; i++) {
            int f = tid + i * 128;
            int row = f >> 4, seg = (f & 15) * 8;
            cp_async16(&stB[row * 136 + seg], Ct + row * 128 + seg);
        }
        cp_commit();
        #pragma unroll
        for (int mt = 0; mt < 4; mt++) {
            int rl = wm + mt * 16 + g;
            #pragma unroll
            for (int nt = 0; nt < 8; nt++) {
                int c = wn + nt * 8 + t4 * 2;
                *(uint32_t*)&stA[rl * 136 + c]       = f2_to_h2(acc[mt][nt][0], acc[mt][nt][1]);
                *(uint32_t*)&stA[(rl + 8) * 136 + c] = f2_to_h2(acc[mt][nt][2], acc[mt][nt][3]);
            }
        }
        asm volatile("cp.async.wait_group 0;" ::: "memory");
        __syncthreads();

        float ac2[4][8][4];
        #pragma unroll
        for (int i = 0; i < 4; i++)
            #pragma unroll
            for (int j = 0; j < 8; j++)
                #pragma unroll
                for (int k = 0; k < 4; k++) ac2[i][j][k] = 0.f;

        #pragma unroll
        for (int kk = 0; kk < 128; kk += 16) {
            uint32_t a[4][4], b[8][2];
            #pragma unroll
            for (int mt = 0; mt < 4; mt++) {
                int mb = wm + mt * 16 + g;
                a[mt][0] = *(const uint32_t*)&stA[mb * 136 + kk + 2 * t4];
                a[mt][1] = *(const uint32_t*)&stA[(mb + 8) * 136 + kk + 2 * t4];
                a[mt][2] = *(const uint32_t*)&stA[mb * 136 + kk + 2 * t4 + 8];
                a[mt][3] = *(const uint32_t*)&stA[(mb + 8) * 136 + kk + 2 * t4 + 8];
            }
            #pragma unroll
            for (int nt = 0; nt < 8; nt++) {
                int nb = wn + nt * 8 + g;
                int kr = kk + 2 * t4;
                b[nt][0] = pack_h2(&stB[kr * 136 + nb],       &stB[(kr + 1) * 136 + nb]);
                b[nt][1] = pack_h2(&stB[(kr + 8) * 136 + nb], &stB[(kr + 9) * 136 + nb]);
            }
            #pragma unroll
            for (int mt = 0; mt < 4; mt++)
                #pragma unroll
                for (int nt = 0; nt < 8; nt++) {
                    asm volatile(
                        "mma.sync.aligned.m16n8k16.row.col.f32.f16.f16.f32 "
                        "{%0,%1,%2,%3}, {%4,%5,%6,%7}, {%8,%9}, {%0,%1,%2,%3};"
                        : "+f"(ac2[mt][nt][0]), "+f"(ac2[mt][nt][1]),
                          "+f"(ac2[mt][nt][2]), "+f"(ac2[mt][nt][3])
                        : "r"(a[mt][0]), "r"(a[mt][1]), "r"(a[mt][2]), "r"(a[mt][3]),
                          "r"(b[nt][0]), "r"(b[nt][1]));
                }
        }
        __half* Ch = (__half*)Cb;
        #pragma unroll
        for (int mt = 0; mt < 4; mt++) {
            int r0g = row0 + wm + mt * 16 + g;
            #pragma unroll
            for (int nt = 0; nt < 8; nt++) {
                int c0g = wn + nt * 8 + t4 * 2;
                *(uint32_t*)(Ch + (long long)r0g * ldc + c0g)       = f2_to_h2(ac2[mt][nt][0], ac2[mt][nt][1]);
                *(uint32_t*)(Ch + (long long)(r0g + 8) * ldc + c0g) = f2_to_h2(ac2[mt][nt][2], ac2[mt][nt][3]);
            }
        }
        return;
    }

    if (CT) {
        __half* st = (__half*)smem;
        #pragma unroll
        for (int mt = 0; mt < 4; mt++) {
            int rl = wm + mt * 16 + g;
            #pragma unroll
            for (int nt = 0; nt < 8; nt++) {
                int c = wn + nt * 8 + t4 * 2;
                st[c * 136 + rl]            = __float2half_rn(acc[mt][nt][0] * alpha);
                st[(c + 1) * 136 + rl]      = __float2half_rn(acc[mt][nt][1] * alpha);
                st[c * 136 + rl + 8]        = __float2half_rn(acc[mt][nt][2] * alpha);
                st[(c + 1) * 136 + rl + 8]  = __float2half_rn(acc[mt][nt][3] * alpha);
            }
        }
        __syncthreads();
        #pragma unroll
        for (int it2 = 0; it2 < 16; it2++) {
            int i = tid + it2 * 128;
            int d = i >> 4, seg = (i & 15) * 8;
            *(uint4*)(Ct + (long long)d * ldt + row0 + seg) = *(const uint4*)&st[d * 136 + seg];
        }
        return;
    }

    #pragma unroll
    for (int mt = 0; mt < 4; mt++) {
        int r0g = row0 + wm + mt * 16 + g;
        #pragma unroll
        for (int nt = 0; nt < 8; nt++) {
            int c0g = col0 + wn + nt * 8 + t4 * 2;
            float v0 = acc[mt][nt][0] * alpha;
            float v1 = acc[mt][nt][1] * alpha;
            float v2 = acc[mt][nt][2] * alpha;
            float v3 = acc[mt][nt][3] * alpha;
            if (CH) {
                __half* Ch = (__half*)Cb;
                *(uint32_t*)(Ch + (long long)r0g * ldc + c0g)       = f2_to_h2(v0, v1);
                *(uint32_t*)(Ch + (long long)(r0g + 8) * ldc + c0g) = f2_to_h2(v2, v3);
            } else {
                float* Cf = (float*)Cb;
                if (R) {
                    v0 += R[(long long)r0g * ldc + c0g];
                    v1 += R[(long long)r0g * ldc + c0g + 1];
                    v2 += R[(long long)(r0g + 8) * ldc + c0g];
                    v3 += R[(long long)(r0g + 8) * ldc + c0g + 1];
                }
                *(float2*)(Cf + (long long)r0g * ldc + c0g)       = make_float2(v0, v1);
                *(float2*)(Cf + (long long)(r0g + 8) * ldc + c0g) = make_float2(v2, v3);
            }
        }
    }
}

// ---------------------------------------------------------------------------
// Kernels
// ---------------------------------------------------------------------------

// All 5 projections, fp16 in/out. z in [0,160): p = z/32, zz = z%32 = (b,h).
__global__ void __launch_bounds__(128, 3)
proj_gemm(const __half* __restrict__ xh, const __half* __restrict__ wh,
          __half* qt, __half* kt, __half* qf, __half* kf, __half* vvT) {
    extern __shared__ char dynsmem[];
    const int z = blockIdx.z;
    const int p = z >> 5, zz = z & 31;
    const __half* Ab = xh + (long long)p * 4194304 + (long long)(zz >> 3) * Nn * Dd;
    const __half* Bb = wh + (long long)p * 1048576 + (long long)(zz & 7) * DKk * Dd;
    const int row0 = blockIdx.y * TBM;
    if (p == 4) {
        gemm_f16<64, 2, 0, 0, 1, 1, 0, 0>(dynsmem, Ab, Bb, nullptr, nullptr,
                                   vvT + (long long)zz * DKk * Nn, Nn, nullptr, 0,
                                   Dd, Dd, Dd, DKk, 1.0f, row0, 0);
    } else {
        __half* C;
        switch (p) {
            case 0: C = qt; break;  case 1: C = kt; break;
            case 2: C = qf; break;  default: C = kf; break;
        }
        gemm_f16<64, 2, 0, 0, 1, 0, 0, 0>(dynsmem, Ab, Bb,
                                   C + (long long)zz * Nn * DKk, nullptr, nullptr, 0, nullptr, 0,
                                   Dd, Dd, Dd, DKk, 1.0f, row0, 0);
    }
}

// feature split-K partials (blocks 0..255, scheduled first) +
// time logits (blocks 256..2303, fp16 out, scaled). TBK=32 path (K=128).
__global__ void __launch_bounds__(128, 3)
fused_logits(const __half* __restrict__ qt, const __half* __restrict__ kt,
             const __half* __restrict__ qf, const __half* __restrict__ kf,
             __half* __restrict__ at16, float* __restrict__ afp, float alpha) {
    extern __shared__ char dynsmem[];
    const int bx = blockIdx.x;
    if (bx < 256) {
        const int e = bx;
        const int z = e >> 3, sub = e & 7;
        const long long base = (long long)z * Nn * DKk + (long long)sub * 128 * DKk;
        gemm_f16<32, 3, 1, 1, 0, 0, 0, 0>(dynsmem,
                        qf + base, kf + base,
                        afp + (long long)e * DKk * DKk, nullptr, nullptr, 0, nullptr, 0,
                        128, DKk, DKk, DKk, alpha, 0, 0);
    } else {
        const int t = bx - 256;
        const int z = t >> 6, rem = t & 63;
        gemm_f16<32, 3, 0, 0, 1, 0, 0, 0>(dynsmem,
                        qt + (long long)z * Nn * DKk,
                        kt + (long long)z * Nn * DKk,
                        at16 + (long long)z * Nn * Nn, nullptr, nullptr, 0, nullptr, 0,
                        DKk, DKk, DKk, Nn, alpha,
                        (rem >> 3) * TBM, (rem & 7) * TBN);
    }
}

// fused: prefc tile = (at16 @ vvT^T) @ af16, written to prefc; echoes attn fp32.
__global__ void __launch_bounds__(128, 3)
attnv_fused(const __half* __restrict__ at16, const __half* __restrict__ vvT,
            const __half* __restrict__ af16, __half* __restrict__ prefc,
            float* __restrict__ at_out) {
    extern __shared__ char dynsmem[];
    const int z = blockIdx.z;
    gemm_f16<64, 2, 0, 0, 1, 0, 1, 1>(dynsmem,
                    at16 + (long long)z * Nn * Nn,
                    vvT + (long long)z * DKk * Nn,
                    prefc + (long long)(z >> 3) * Nn * Dd + (z & 7) * DKk,
                    nullptr,
                    (__half*)(af16 + (long long)z * DKk * DKk), 0,
                    at_out + (long long)z * Nn * Nn, Nn,
                    Nn, Nn, Nn, Dd, 1.0f, blockIdx.y * TBM, 0);
}

// preln = prefc @ w_fc^T + v
__global__ void __launch_bounds__(128, 3)
fc_gemm(const __half* __restrict__ prefc, const __half* __restrict__ wfc,
        float* __restrict__ preln, const float* __restrict__ v) {
    extern __shared__ char dynsmem[];
    gemm_f16<64, 2, 0, 0, 0, 0, 0, 0>(dynsmem, prefc, wfc, preln, v, nullptr, 0, nullptr, 0,
                    Dd, Dd, Dd, Dd, 1.0f,
                    blockIdx.y * TBM, blockIdx.x * TBN);
}

// ---------------------------------------------------------------------------
__device__ __forceinline__ float block_reduce(float v, bool is_max) {
    __shared__ float sh[32];
    int lane = threadIdx.x & 31, w = threadIdx.x >> 5;
    #pragma unroll
    for (int o = 16; o > 0; o >>= 1) {
        float o2 = __shfl_xor_sync(0xffffffff, v, o);
        v = is_max ? fmaxf(v, o2) : v + o2;
    }
    if (lane == 0) sh[w] = v;
    __syncthreads();
    int nw = (blockDim.x + 31) >> 5;
    v = (lane < nw) ? sh[lane] : (is_max ? -3.4e38f : 0.f);
    if (w == 0) {
        #pragma unroll
        for (int o = 16; o > 0; o >>= 1) {
            float o2 = __shfl_xor_sync(0xffffffff, v, o);
            v = is_max ? fmaxf(v, o2) : v + o2;
        }
        if (lane == 0) sh[0] = v;
    }
    __syncthreads();
    v = sh[0];
    __syncthreads();
    return v;
}

// Merged softmax launch. Time rows: no max-subtraction (logits bounded);
// masked lanes contribute 0. Writes normalized fp16 in place.
__global__ void softmax_all_kernel(__half* __restrict__ at16,
                                   const int* __restrict__ mask,
                                   const float* __restrict__ afp,
                                   float* __restrict__ S,
                                   __half* __restrict__ S16) {
    if (blockIdx.x < 32768) {
        const int r = blockIdx.x;
        const int b = r / (Hh * Nn);
        const int n = r % Nn;
        __half* row16 = at16 + (long long)r * Nn;
        const int* mrow = mask + ((long long)b * Nn + n) * Nn;
        const int j0 = threadIdx.x * 8;

        uint4 lv = *(const uint4*)(row16 + j0);
        __half2 h0 = *(__half2*)&lv.x, h1 = *(__half2*)&lv.y;
        __half2 h2 = *(__half2*)&lv.z, h3 = *(__half2*)&lv.w;
        int4 m0 = __ldg((const int4*)(mrow + j0));
        int4 m1 = __ldg((const int4*)(mrow + j0 + 4));
        float x[8];
        x[0] = m0.x == 0 ? 0.f : __expf(__low2float(h0));
        x[1] = m0.y == 0 ? 0.f : __expf(__high2float(h0));
        x[2] = m0.z == 0 ? 0.f : __expf(__low2float(h1));
        x[3] = m0.w == 0 ? 0.f : __expf(__high2float(h1));
        x[4] = m1.x == 0 ? 0.f : __expf(__low2float(h2));
        x[5] = m1.y == 0 ? 0.f : __expf(__high2float(h2));
        x[6] = m1.z == 0 ? 0.f : __expf(__low2float(h3));
        x[7] = m1.w == 0 ? 0.f : __expf(__high2float(h3));
        float s = 0.f;
        #pragma unroll
        for (int i = 0; i < 8; i++) s += x[i];
        s = block_reduce(s, false);
        float inv = 1.f / s;
        #pragma unroll
        for (int i = 0; i < 8; i++) x[i] *= inv;
        uint4 ov = make_uint4(f2_to_h2(x[0], x[1]), f2_to_h2(x[2], x[3]),
                              f2_to_h2(x[4], x[5]), f2_to_h2(x[6], x[7]));
        *(uint4*)(row16 + j0) = ov;
    } else {
        const int e = blockIdx.x - 32768;
        const int z = e >> 7;
        const int row = e & 127;
        const int t = threadIdx.x;
        float v = 0.f;
        #pragma unroll
        for (int s8 = 0; s8 < 8; s8++)
            v += afp[(((long long)z * 8 + s8) * DKk + row) * DKk + t];
        float mx = block_reduce(v, true);
        float ex = __expf(v - mx);
        float s = block_reduce(ex, false);
        float o = ex / s;
        __stwt(&S[((long long)z * DKk + row) * DKk + t], o);
        S16[((long long)z * DKk + row) * DKk + t] = __float2half_rn(o);
    }
}

__global__ void layernorm_kernel(const float* __restrict__ X, float* __restrict__ O,
                                 const float* __restrict__ gamma, const float* __restrict__ beta) {
    const int r = blockIdx.x;
    const float* row = X + (long long)r * Dd;
    float* orow = O + (long long)r * Dd;
    const int j0 = threadIdx.x * 4;
    float4 xv = *(const float4*)(row + j0);
    float x[4] = {xv.x, xv.y, xv.z, xv.w};
    float s = x[0] + x[1] + x[2] + x[3];
    float s2 = x[0]*x[0] + x[1]*x[1] + x[2]*x[2] + x[3]*x[3];
    s = block_reduce(s, false);
    s2 = block_reduce(s2, false);
    float mean = s * (1.f / Dd);
    float var = s2 * (1.f / Dd) - mean * mean;
    float inv = rsqrtf(var + EPSf);
    float4 gv = *(const float4*)(gamma + j0);
    float4 bv = *(const float4*)(beta + j0);
    __stwt((float4*)(orow + j0),
           make_float4((x[0] - mean) * inv * gv.x + bv.x,
                       (x[1] - mean) * inv * gv.y + bv.y,
                       (x[2] - mean) * inv * gv.z + bv.z,
                       (x[3] - mean) * inv * gv.w + bv.w));
}

// ---------------------------------------------------------------------------
extern "C" void kernel_launch(void* const* d_in, const int* in_sizes, int n_in,
                              void* d_out, int out_size) {
    const float* q_time    = (const float*)d_in[0];
    const float* k_time    = (const float*)d_in[1];
    const float* q_feature = (const float*)d_in[2];
    const float* k_feature = (const float*)d_in[3];
    const float* v         = (const float*)d_in[4];
    const int*   attn_mask = (const int*)  d_in[5];
    const float* w_qs_time = (const float*)d_in[6];
    const float* w_ks_time = (const float*)d_in[7];
    const float* w_qs_feat = (const float*)d_in[8];
    const float* w_ks_feat = (const float*)d_in[9];
    const float* w_vs      = (const float*)d_in[10];
    const float* w_fc      = (const float*)d_in[11];
    const float* ln_gamma  = (const float*)d_in[12];
    const float* ln_beta   = (const float*)d_in[13];
    float* out = (float*)d_out;

    __half *qt, *kt, *qf, *kf, *vvT, *prefc, *at16, *af16, *wh, *xh;
    float *preln, *afp;
    cudaGetSymbolAddress((void**)&qt,    g_qt);
    cudaGetSymbolAddress((void**)&kt,    g_kt);
    cudaGetSymbolAddress((void**)&qf,    g_qf);
    cudaGetSymbolAddress((void**)&kf,    g_kf);
    cudaGetSymbolAddress((void**)&vvT,   g_vvT);
    cudaGetSymbolAddress((void**)&prefc, g_prefc);
    cudaGetSymbolAddress((void**)&preln, g_preln);
    cudaGetSymbolAddress((void**)&afp,   g_afp);
    cudaGetSymbolAddress((void**)&at16,  g_at16);
    cudaGetSymbolAddress((void**)&af16,  g_af16);
    cudaGetSymbolAddress((void**)&wh,    g_wh);
    cudaGetSymbolAddress((void**)&xh,    g_xh);

    cudaFuncSetAttribute(proj_gemm,   cudaFuncAttributeMaxDynamicSharedMemorySize, SMEM_BIG);
    cudaFuncSetAttribute(fused_logits,cudaFuncAttributeMaxDynamicSharedMemorySize, SMEM_ALL);
    cudaFuncSetAttribute(attnv_fused, cudaFuncAttributeMaxDynamicSharedMemorySize, SMEM_BIG);
    cudaFuncSetAttribute(fc_gemm,     cudaFuncAttributeMaxDynamicSharedMemorySize, SMEM_BIG);

    const float inv_temp = 1.0f / sqrtf((float)DKk);
    const int Z = Bz * Hh;  // 32
    dim3 blk(128);

    // 0) convert weights + inputs to fp16 (single launch)
    cvt_all_kernel<<<6 * 1024 + 5 * 4096, 256>>>(
        w_qs_time, w_ks_time, w_qs_feat, w_ks_feat, w_vs, w_fc,
        q_time, k_time, q_feature, k_feature, v, wh, xh);

    // 1) all projections (fp16 in/out; vv transposed), TBK=64
    {
        dim3 grid(1, Nn / TBM, 5 * Z);
        proj_gemm<<<grid, blk, SMEM_BIG>>>(xh, wh, qt, kt, qf, kf, vvT);
    }

    float* at = out + AT_OFF;
    float* af = out + AF_OFF;

    // 2) feature split-K partials (first) + time logits (fp16), TBK=32
    fused_logits<<<256 + 2048, blk, SMEM_ALL>>>(qt, kt, qf, kf, at16, afp, inv_temp);

    // 3) both softmaxes in one launch
    softmax_all_kernel<<<32768 + 4096, 128>>>(at16, attn_mask, afp, af, af16);

    // 4) prefc = (attn @ v) @ af, fused, TBK=64; echoes fp32 attn to d_out
    {
        dim3 grid(1, Nn / TBM, Z);
        attnv_fused<<<grid, blk, SMEM_BIG>>>(at16, vvT, af16, prefc, at);
    }

    // 5) preln = prefc @ w_fc^T + v, TBK=64
    {
        dim3 grid(Dd / TBN, (Bz * Nn) / TBM, 1);
        fc_gemm<<<grid, blk, SMEM_BIG>>>(prefc, wh + 5u * 1048576u, preln, v);
    }

    // 6) LayerNorm
    layernorm_kernel<<<Bz * Nn, 256>>>(preln, out, ln_gamma, ln_beta);
}